// round 4
// baseline (speedup 1.0000x reference)
#include <cuda_runtime.h>

// Problem constants
#define HIDDEN  1024
#define NHEADS  16
#define HD      64
#define BB      2
#define TSEQ    2048
#define MROWS   (BB * TSEQ)          // 4096

// ---------------- scratch (device globals: no allocation allowed) ----------
__device__ float g_q[BB * NHEADS * TSEQ * HD];     // [B,H,T,D]
__device__ float g_k[BB * NHEADS * TSEQ * HD];
__device__ float g_v[BB * NHEADS * TSEQ * HD];
__device__ float g_att[MROWS * HIDDEN];            // [B,T,C]

typedef unsigned long long u64;

// ---------------- f32x2 helpers (Blackwell packed fp32) ---------------------
__device__ __forceinline__ void ffma2(u64& d, u64 a, u64 b) {
    asm("fma.rn.f32x2 %0, %1, %2, %0;" : "+l"(d) : "l"(a), "l"(b));
}
__device__ __forceinline__ void fmul2(u64& d, u64 a) {
    asm("mul.rn.f32x2 %0, %0, %1;" : "+l"(d) : "l"(a));
}
__device__ __forceinline__ u64 pkdup(float x) {
    u64 r; asm("mov.b64 %0, {%1, %1};" : "=l"(r) : "f"(x)); return r;
}
__device__ __forceinline__ void upk(u64 x, float& a, float& b) {
    asm("mov.b64 {%0, %1}, %2;" : "=f"(a), "=f"(b) : "l"(x));
}
// bare MUFU.EX2 (exact enough for 1e-3 rel-err; ex2(-1e30) -> 0 for the mask)
__device__ __forceinline__ float ex2(float x) {
    float r; asm("ex2.approx.f32 %0, %1;" : "=f"(r) : "f"(x)); return r;
}
// cp.async 16B (LDGSTS): gmem -> smem without register staging
__device__ __forceinline__ void cpa16(void* s, const void* g) {
    unsigned sa = (unsigned)__cvta_generic_to_shared(s);
    asm volatile("cp.async.cg.shared.global [%0], [%1], 16;\n" :: "r"(sa), "l"(g));
}
__device__ __forceinline__ void cpa_commit() {
    asm volatile("cp.async.commit_group;\n");
}
__device__ __forceinline__ void cpa_wait0() {
    asm volatile("cp.async.wait_group 0;\n");
}

// ---------------- GEMM: out[M,N] = A[M,1024] @ W[1024,N] + bias -------------
// BM=128, BN=128, BK=16, 256 threads, 8x8 per thread via FFMA2.
// A is stored in SMEM pre-duplicated as f32x2 {a,a} pairs (no packing MOVs in
// the inner loop). Double-buffered SMEM with register prefetch: one
// __syncthreads per k-tile, global loads overlap compute.
// scatter=1: N=3072, write q/k/v scratch in [B,H,T,D] layout.
// scatter=0: N=1024, A==nullptr means read g_att; write `out` row-major.
#define GBM 128
#define GBN 128
#define GBK 16
#define PADM 130   // As row stride in u64: 16B-aligned, staggers STS banks
#define NKT (HIDDEN / GBK)  // 64 k-tiles

// dynamic smem layout (bytes):
//   As: 2 * GBK * PADM * 8  = 33280
//   Bs: 2 * GBK * GBN  * 4  = 16384
#define GEMM_SMEM (2 * GBK * PADM * 8 + 2 * GBK * GBN * 4)

__global__ __launch_bounds__(256, 2)
void csa_gemm_f32x2(const float* __restrict__ A, const float* __restrict__ W,
                    const float* __restrict__ bias, float* __restrict__ out,
                    int N, int scatter)
{
    extern __shared__ __align__(16) char gsm[];
    u64*   As = (u64*)gsm;                                // [2][GBK][PADM]
    float* Bs = (float*)(gsm + 2 * GBK * PADM * 8);       // [2][GBK][GBN]

    const float* Ap = A ? A : (const float*)g_att;

    int tid = threadIdx.x;
    int tx = tid & 15, ty = tid >> 4;
    int row0 = blockIdx.y * GBM;
    int col0 = blockIdx.x * GBN;

    // loader indices (each thread handles 2 float4 of A, 2 float4 of W per tile)
    int am[2], akq[2], wk[2], wn4[2];
#pragma unroll
    for (int l = 0; l < 2; l++) {
        int idx = tid + l * 256;          // 0..511
        am[l]  = idx >> 2;                // 0..127
        akq[l] = (idx & 3) << 2;          // 0,4,8,12
        wk[l]  = idx >> 5;                // 0..15
        wn4[l] = (idx & 31) << 2;         // 0..124
    }

    u64 acc[8][4];
#pragma unroll
    for (int i = 0; i < 8; i++)
#pragma unroll
        for (int j = 0; j < 4; j++) acc[i][j] = 0ull;

    float4 pa[2], pb[2];

    // ---- prologue: load tile 0 into regs, store to buffer 0 ----
#pragma unroll
    for (int l = 0; l < 2; l++) {
        pa[l] = *(const float4*)&Ap[(size_t)(row0 + am[l]) * HIDDEN + akq[l]];
        pb[l] = *(const float4*)&W[(size_t)wk[l] * N + col0 + wn4[l]];
    }
#pragma unroll
    for (int l = 0; l < 2; l++) {
        u64* as = &As[0 * GBK * PADM];
        as[(akq[l] + 0) * PADM + am[l]] = pkdup(pa[l].x);
        as[(akq[l] + 1) * PADM + am[l]] = pkdup(pa[l].y);
        as[(akq[l] + 2) * PADM + am[l]] = pkdup(pa[l].z);
        as[(akq[l] + 3) * PADM + am[l]] = pkdup(pa[l].w);
        *(float4*)&Bs[0 * GBK * GBN + wk[l] * GBN + wn4[l]] = pb[l];
    }
    __syncthreads();

    for (int t = 0; t < NKT; t++) {
        int buf = t & 1;
        // prefetch tile t+1 into registers (overlaps with compute below)
        if (t + 1 < NKT) {
            int k0 = (t + 1) * GBK;
#pragma unroll
            for (int l = 0; l < 2; l++) {
                pa[l] = *(const float4*)&Ap[(size_t)(row0 + am[l]) * HIDDEN + k0 + akq[l]];
                pb[l] = *(const float4*)&W[(size_t)(k0 + wk[l]) * N + col0 + wn4[l]];
            }
        }

        // compute on buffer `buf`
        const u64*   as = &As[buf * GBK * PADM];
        const float* bs = &Bs[buf * GBK * GBN];
#pragma unroll
        for (int k = 0; k < GBK; k++) {
            const u64* ar = &as[k * PADM + ty * 8];
            ulonglong2 a01 = *(const ulonglong2*)(ar + 0);
            ulonglong2 a23 = *(const ulonglong2*)(ar + 2);
            ulonglong2 a45 = *(const ulonglong2*)(ar + 4);
            ulonglong2 a67 = *(const ulonglong2*)(ar + 6);
            ulonglong2 b0 = *(const ulonglong2*)&bs[k * GBN + tx * 8];
            ulonglong2 b1 = *(const ulonglong2*)&bs[k * GBN + tx * 8 + 4];
            u64 bb[4] = { b0.x, b0.y, b1.x, b1.y };
            u64 ad[8] = { a01.x, a01.y, a23.x, a23.y, a45.x, a45.y, a67.x, a67.y };
#pragma unroll
            for (int i = 0; i < 8; i++)
#pragma unroll
                for (int j = 0; j < 4; j++) ffma2(acc[i][j], ad[i], bb[j]);
        }

        // store prefetched tile into the other buffer (touches only buf^1,
        // which no thread reads during compute(t); sync below publishes it)
        if (t + 1 < NKT) {
            u64*   asn = &As[(buf ^ 1) * GBK * PADM];
            float* bsn = &Bs[(buf ^ 1) * GBK * GBN];
#pragma unroll
            for (int l = 0; l < 2; l++) {
                asn[(akq[l] + 0) * PADM + am[l]] = pkdup(pa[l].x);
                asn[(akq[l] + 1) * PADM + am[l]] = pkdup(pa[l].y);
                asn[(akq[l] + 2) * PADM + am[l]] = pkdup(pa[l].z);
                asn[(akq[l] + 3) * PADM + am[l]] = pkdup(pa[l].w);
                *(float4*)&bsn[wk[l] * GBN + wn4[l]] = pb[l];
            }
            __syncthreads();
        }
    }

    // epilogue
    int colb = col0 + tx * 8;
    float bi[8];
#pragma unroll
    for (int j = 0; j < 8; j++) bi[j] = bias[colb + j];

    if (!scatter) {
#pragma unroll
        for (int i = 0; i < 8; i++) {
            int r = row0 + ty * 8 + i;
            float v[8];
#pragma unroll
            for (int j = 0; j < 4; j++) upk(acc[i][j], v[2 * j], v[2 * j + 1]);
#pragma unroll
            for (int j = 0; j < 8; j++) v[j] += bi[j];
            float* o = &out[(size_t)r * N + colb];
            *(float4*)&o[0] = make_float4(v[0], v[1], v[2], v[3]);
            *(float4*)&o[4] = make_float4(v[4], v[5], v[6], v[7]);
        }
    } else {
        // column -> (which, head, d). 8 consecutive cols stay inside one head.
        int which = colb >> 10;
        int cc    = colb & 1023;
        int h     = cc >> 6;
        int dbase = cc & 63;
        float* dst = (which == 0) ? g_q : ((which == 1) ? g_k : g_v);
#pragma unroll
        for (int i = 0; i < 8; i++) {
            int r  = row0 + ty * 8 + i;
            int b  = r >> 11;          // / 2048
            int t  = r & 2047;
            float v[8];
#pragma unroll
            for (int j = 0; j < 4; j++) upk(acc[i][j], v[2 * j], v[2 * j + 1]);
#pragma unroll
            for (int j = 0; j < 8; j++) v[j] += bi[j];
            size_t base = (((size_t)(b * NHEADS + h) * TSEQ) + t) * HD + dbase;
            *(float4*)&dst[base]     = make_float4(v[0], v[1], v[2], v[3]);
            *(float4*)&dst[base + 4] = make_float4(v[4], v[5], v[6], v[7]);
        }
    }
}

// ---------------- Flash attention (causal), fp32 ----------------------------
// grid = (T/64, B*H), 256 threads. Thread (r=tid/16, c=tid%16) owns
// S rows {r,r+16,r+32,r+48} x cols {c,c+16,c+32,c+48}, O cols d=4c..4c+3.
// P tile lives in SMEM pre-duplicated as {p,p} u64 pairs (PV loop has zero
// packing MOVs). K/V tiles are cp.async ping-ponged in place: K(kt+1) loads
// during the PV loop (Ks dead after mid-barrier), V(kt+1) loads during the
// next QK loop (Vs dead after end barrier). qt is reversed so the heaviest
// causal tiles are scheduled first (LPT).
#define AST 68     // Q/K/V smem row stride (floats): 16B-aligned, low-conflict
#define PST 66     // P smem row stride (u64)
#define ATTN_SMEM (3 * 64 * AST * 4 + 64 * PST * 8)   // 85760 B

__global__ __launch_bounds__(256, 2)
void csa_attn_kernel()
{
    extern __shared__ float sm[];
    float* Qs = sm;
    float* Ks = sm + 64 * AST;
    float* Vs = sm + 2 * 64 * AST;
    u64*   Ps = (u64*)(sm + 3 * 64 * AST);

    int bh  = blockIdx.y;
    int qt  = gridDim.x - 1 - blockIdx.x;   // heaviest-first scheduling
    int tid = threadIdx.x;
    int r = tid >> 4, c = tid & 15;

    const float* qb = g_q + (size_t)bh * TSEQ * HD;
    const float* kb = g_k + (size_t)bh * TSEQ * HD;
    const float* vb = g_v + (size_t)bh * TSEQ * HD;
    int q0 = qt * 64;

    // per-thread loader slice: 4 rows x one float4 each (row = tid/16 + 16l)
    int lrowi[4], lc4;
    lc4 = (tid & 15) << 2;
#pragma unroll
    for (int l = 0; l < 4; l++) lrowi[l] = (tid >> 4) + 16 * l;

    // load Q tile (64x64) + async K0,V0
#pragma unroll
    for (int l = 0; l < 4; l++) {
        int row = lrowi[l];
        *(float4*)&Qs[row * AST + lc4] =
            *(const float4*)&qb[(size_t)(q0 + row) * HD + lc4];
        cpa16(&Ks[row * AST + lc4], &kb[(size_t)row * HD + lc4]);
        cpa16(&Vs[row * AST + lc4], &vb[(size_t)row * HD + lc4]);
    }
    cpa_commit();

    float mrow[4], lrow[4];
    u64 oac[4][2];
#pragma unroll
    for (int i = 0; i < 4; i++) {
        mrow[i] = -1e30f; lrow[i] = 0.0f;
        oac[i][0] = 0ull; oac[i][1] = 0ull;
    }

    const float SC = 0.125f * 1.4426950408889634f;  // 1/sqrt(64) * log2(e)

    for (int kt = 0; kt <= qt; ++kt) {
        // pending cp.async for this iteration's K (and V) must land
        cpa_wait0();
        __syncthreads();

        // S = Q K^T : f32x2 pair-accumulate along d, operands pre-packed in smem
        u64 sac[4][4];
#pragma unroll
        for (int i = 0; i < 4; i++)
#pragma unroll
            for (int j = 0; j < 4; j++) sac[i][j] = 0ull;

#pragma unroll
        for (int d4 = 0; d4 < 16; ++d4) {
            ulonglong2 qv[4], kv[4];
#pragma unroll
            for (int i = 0; i < 4; i++)
                qv[i] = *(const ulonglong2*)&Qs[(r + 16 * i) * AST + d4 * 4];
#pragma unroll
            for (int j = 0; j < 4; j++)
                kv[j] = *(const ulonglong2*)&Ks[(c + 16 * j) * AST + d4 * 4];
#pragma unroll
            for (int i = 0; i < 4; i++)
#pragma unroll
                for (int j = 0; j < 4; j++) {
                    ffma2(sac[i][j], qv[i].x, kv[j].x);
                    ffma2(sac[i][j], qv[i].y, kv[j].y);
                }
        }

        // online softmax (log2 domain, bare MUFU.EX2)
        int k0 = kt * 64;
        float p[4][4], alpha[4];
#pragma unroll
        for (int i = 0; i < 4; i++) {
            int qrow = q0 + r + 16 * i;
            float sv[4];
#pragma unroll
            for (int j = 0; j < 4; j++) {
                float a, b; upk(sac[i][j], a, b);
                float s = (a + b) * SC;
                int kcol = k0 + c + 16 * j;
                sv[j] = (kcol <= qrow) ? s : -1e30f;
            }
            float mloc = fmaxf(fmaxf(sv[0], sv[1]), fmaxf(sv[2], sv[3]));
#pragma unroll
            for (int w = 1; w < 16; w <<= 1)
                mloc = fmaxf(mloc, __shfl_xor_sync(0xffffffffu, mloc, w, 16));
            float mnew = fmaxf(mrow[i], mloc);
            float al = ex2(mrow[i] - mnew);
            mrow[i] = mnew;
            float ps = 0.0f;
#pragma unroll
            for (int j = 0; j < 4; j++) { p[i][j] = ex2(sv[j] - mnew); ps += p[i][j]; }
#pragma unroll
            for (int w = 1; w < 16; w <<= 1)
                ps += __shfl_xor_sync(0xffffffffu, ps, w, 16);
            lrow[i] = lrow[i] * al + ps;
            alpha[i] = al;
        }
        // rescale running O
#pragma unroll
        for (int i = 0; i < 4; i++) {
            u64 ap = pkdup(alpha[i]);
            fmul2(oac[i][0], ap);
            fmul2(oac[i][1], ap);
        }
        // publish P pre-duplicated as {p,p} pairs
#pragma unroll
        for (int i = 0; i < 4; i++)
#pragma unroll
            for (int j = 0; j < 4; j++)
                Ps[(r + 16 * i) * PST + (c + 16 * j)] = pkdup(p[i][j]);
        __syncthreads();   // publishes P; everyone is also done reading Ks

        // Ks is dead now: overlap K(kt+1) load with the PV loop below
        if (kt + 1 <= qt) {
            int kn0 = (kt + 1) * 64;
#pragma unroll
            for (int l = 0; l < 4; l++) {
                int row = lrowi[l];
                cpa16(&Ks[row * AST + lc4], &kb[(size_t)(kn0 + row) * HD + lc4]);
            }
            cpa_commit();
        }

        // O += P @ V  (thread owns d = 4c..4c+3); P loads are LDS.64 broadcast
#pragma unroll 4
        for (int jj = 0; jj < 64; ++jj) {
            ulonglong2 vv = *(const ulonglong2*)&Vs[jj * AST + (c << 2)];
#pragma unroll
            for (int i = 0; i < 4; i++) {
                u64 pd = Ps[(r + 16 * i) * PST + jj];
                ffma2(oac[i][0], pd, vv.x);
                ffma2(oac[i][1], pd, vv.y);
            }
        }
        __syncthreads();   // everyone done reading Vs and Ps

        // Vs is dead now: overlap V(kt+1) load with the next iteration's QK
        if (kt + 1 <= qt) {
            int kn0 = (kt + 1) * 64;
#pragma unroll
            for (int l = 0; l < 4; l++) {
                int row = lrowi[l];
                cpa16(&Vs[row * AST + lc4], &vb[(size_t)(kn0 + row) * HD + lc4]);
            }
            cpa_commit();
        }
    }

    // epilogue: normalize, write [B,T,C]
    int b = bh >> 4, h = bh & 15;
#pragma unroll
    for (int i = 0; i < 4; i++) {
        float inv = 1.0f / lrow[i];
        float o0, o1, o2, o3;
        upk(oac[i][0], o0, o1);
        upk(oac[i][1], o2, o3);
        int qrow = q0 + r + 16 * i;
        *(float4*)&g_att[((size_t)(b * TSEQ + qrow)) * HIDDEN + h * HD + (c << 2)] =
            make_float4(o0 * inv, o1 * inv, o2 * inv, o3 * inv);
    }
}

// ---------------- launch -----------------------------------------------------
extern "C" void kernel_launch(void* const* d_in, const int* in_sizes, int n_in,
                              void* d_out, int out_size)
{
    const float* x     = (const float*)d_in[0];
    const float* w_qkv = (const float*)d_in[1];
    const float* b_qkv = (const float*)d_in[2];
    const float* w_out = (const float*)d_in[3];
    const float* b_out = (const float*)d_in[4];
    float* out = (float*)d_out;

    cudaFuncSetAttribute(csa_attn_kernel,
                         cudaFuncAttributeMaxDynamicSharedMemorySize, ATTN_SMEM);
    cudaFuncSetAttribute(csa_gemm_f32x2,
                         cudaFuncAttributeMaxDynamicSharedMemorySize, GEMM_SMEM);

    dim3 blk(256);
    // 1) QKV GEMM + bias, scattered into [B,H,T,D] q/k/v scratch
    csa_gemm_f32x2<<<dim3((3 * HIDDEN) / GBN, MROWS / GBM), blk, GEMM_SMEM>>>(
        x, w_qkv, b_qkv, nullptr, 3 * HIDDEN, 1);
    // 2) causal flash attention -> g_att [B,T,C]
    csa_attn_kernel<<<dim3(TSEQ / 64, BB * NHEADS), blk, ATTN_SMEM>>>();
    // 3) output projection + bias -> d_out
    csa_gemm_f32x2<<<dim3(HIDDEN / GBN, MROWS / GBM), blk, GEMM_SMEM>>>(
        nullptr, w_out, b_out, out, HIDDEN, 0);
}

// round 7
// speedup vs baseline: 1.7512x; 1.7512x over previous
#include <cuda_runtime.h>
#include <cstdint>

// Problem constants
#define HIDDEN  1024
#define NHEADS  16
#define HD      64
#define BB      2
#define TSEQ    2048
#define MROWS   (BB * TSEQ)          // 4096

// ---------------- scratch (device globals: no allocation allowed) ----------
__device__ float g_q[BB * NHEADS * TSEQ * HD];     // [B,H,T,D]
__device__ float g_k[BB * NHEADS * TSEQ * HD];
__device__ float g_v[BB * NHEADS * TSEQ * HD];
__device__ float g_att[MROWS * HIDDEN];            // [B,T,C]

typedef unsigned long long u64;

// ---------------- f32x2 helpers (Blackwell packed fp32) ---------------------
__device__ __forceinline__ void ffma2(u64& d, u64 a, u64 b) {
    asm("fma.rn.f32x2 %0, %1, %2, %0;" : "+l"(d) : "l"(a), "l"(b));
}
__device__ __forceinline__ void fmul2(u64& d, u64 a) {
    asm("mul.rn.f32x2 %0, %0, %1;" : "+l"(d) : "l"(a));
}
__device__ __forceinline__ u64 pkdup(float x) {
    u64 r; asm("mov.b64 %0, {%1, %1};" : "=l"(r) : "f"(x)); return r;
}
__device__ __forceinline__ void upk(u64 x, float& a, float& b) {
    asm("mov.b64 {%0, %1}, %2;" : "=f"(a), "=f"(b) : "l"(x));
}
// bare MUFU.EX2 (exact enough for 1e-3 rel-err; ex2(-1e30) -> 0 for the mask)
__device__ __forceinline__ float ex2(float x) {
    float r; asm("ex2.approx.f32 %0, %1;" : "=f"(r) : "f"(x)); return r;
}
// cp.async 16B (LDGSTS): gmem -> smem without register staging
__device__ __forceinline__ void cpa16(void* s, const void* g) {
    unsigned sa = (unsigned)__cvta_generic_to_shared(s);
    asm volatile("cp.async.cg.shared.global [%0], [%1], 16;\n" :: "r"(sa), "l"(g));
}
__device__ __forceinline__ void cpa_commit() {
    asm volatile("cp.async.commit_group;\n");
}
__device__ __forceinline__ void cpa_wait0() {
    asm volatile("cp.async.wait_group 0;\n");
}
// tf32 round-to-nearest of an f32 (kept in f32 container)
__device__ __forceinline__ float tf32r(float x) {
    float r; asm("cvt.rna.tf32.f32 %0, %1;" : "=f"(r) : "f"(x)); return r;
}
// m16n8k8 tf32 MMA, fp32 accumulate (legacy warp-level path on sm_103a)
__device__ __forceinline__ void mma_tf32(float* c, const uint32_t* a, const uint32_t* b) {
    asm volatile(
        "mma.sync.aligned.m16n8k8.row.col.f32.tf32.tf32.f32 "
        "{%0,%1,%2,%3}, {%4,%5,%6,%7}, {%8,%9}, {%0,%1,%2,%3};\n"
        : "+f"(c[0]), "+f"(c[1]), "+f"(c[2]), "+f"(c[3])
        : "r"(a[0]), "r"(a[1]), "r"(a[2]), "r"(a[3]), "r"(b[0]), "r"(b[1]));
}

// ---------------- GEMM (tf32 tensor): out[M,N] = A[M,1024]@W[1024,N]+bias ---
// BM=128, BN=128, BK=16, 256 threads = 8 warps in a 2(m) x 4(n) grid.
// Warp tile 64x32 = 4x4 m16n8k8 fragments. fp32 accumulate; inputs rounded to
// tf32 (cvt.rna) at the SMEM staging store. Double-buffered SMEM + register
// prefetch, one __syncthreads per k-tile.
// scatter=1: N=3072, write q/k/v scratch in [B,H,T,D] layout.
// scatter=0: N=1024, A==nullptr means read g_att; write `out` row-major.
#define GBM 128
#define GBN 128
#define GBK 16
#define ASK 20     // As row stride (floats): banks (m*20+k)%32 all-distinct
#define BNS 136    // Bs row stride (floats): banks (k*136+n)%32 all-distinct
#define NKT (HIDDEN / GBK)  // 64 k-tiles

__global__ __launch_bounds__(256, 2)
void csa_gemm_tf32(const float* __restrict__ A, const float* __restrict__ W,
                   const float* __restrict__ bias, float* __restrict__ out,
                   int N, int scatter)
{
    __shared__ __align__(16) float As[2][GBM * ASK];   // [m][k]
    __shared__ __align__(16) float Bs[2][GBK * BNS];   // [k][n]

    const float* Ap = A ? A : (const float*)g_att;

    int tid  = threadIdx.x;
    int warp = tid >> 5, lane = tid & 31;
    int wm = warp >> 2, wn = warp & 3;      // 2 x 4 warp grid
    int g  = lane >> 2, t4 = lane & 3;      // groupid / quad-thread
    int row0 = blockIdx.y * GBM;
    int col0 = blockIdx.x * GBN;

    // loader indices (each thread: 2 float4 of A, 2 float4 of W per tile)
    int am[2], akq[2], wk[2], wn4[2];
#pragma unroll
    for (int l = 0; l < 2; l++) {
        int idx = tid + l * 256;          // 0..511
        am[l]  = idx >> 2;                // 0..127
        akq[l] = (idx & 3) << 2;          // 0,4,8,12
        wk[l]  = idx >> 5;                // 0..15
        wn4[l] = (idx & 31) << 2;         // 0..124
    }

    float c[4][4][4];
#pragma unroll
    for (int mf = 0; mf < 4; mf++)
#pragma unroll
        for (int nf = 0; nf < 4; nf++)
#pragma unroll
            for (int e = 0; e < 4; e++) c[mf][nf][e] = 0.0f;

    float4 pa[2], pb[2];

    // ---- prologue: tile 0 -> regs -> buffer 0 (tf32-rounded) ----
#pragma unroll
    for (int l = 0; l < 2; l++) {
        pa[l] = *(const float4*)&Ap[(size_t)(row0 + am[l]) * HIDDEN + akq[l]];
        pb[l] = *(const float4*)&W[(size_t)wk[l] * N + col0 + wn4[l]];
    }
#pragma unroll
    for (int l = 0; l < 2; l++) {
        *(float4*)&As[0][am[l] * ASK + akq[l]] =
            make_float4(tf32r(pa[l].x), tf32r(pa[l].y), tf32r(pa[l].z), tf32r(pa[l].w));
        *(float4*)&Bs[0][wk[l] * BNS + wn4[l]] =
            make_float4(tf32r(pb[l].x), tf32r(pb[l].y), tf32r(pb[l].z), tf32r(pb[l].w));
    }
    __syncthreads();

    for (int t = 0; t < NKT; t++) {
        int buf = t & 1;
        // prefetch tile t+1 into registers (overlaps with compute)
        if (t + 1 < NKT) {
            int k0 = (t + 1) * GBK;
#pragma unroll
            for (int l = 0; l < 2; l++) {
                pa[l] = *(const float4*)&Ap[(size_t)(row0 + am[l]) * HIDDEN + k0 + akq[l]];
                pb[l] = *(const float4*)&W[(size_t)(k0 + wk[l]) * N + col0 + wn4[l]];
            }
        }

        // compute: 2 k8-steps x 4x4 fragments
        const float* as = As[buf];
        const float* bs = Bs[buf];
#pragma unroll
        for (int k8 = 0; k8 < 2; k8++) {
            int kb = k8 * 8;
            uint32_t af[4][4], bf[4][2];
#pragma unroll
            for (int mf = 0; mf < 4; mf++) {
                const float* ap = &as[(wm * 64 + mf * 16 + g) * ASK + kb + t4];
                af[mf][0] = __float_as_uint(ap[0]);           // (g,      t4)
                af[mf][1] = __float_as_uint(ap[8 * ASK]);     // (g+8,    t4)
                af[mf][2] = __float_as_uint(ap[4]);           // (g,      t4+4)
                af[mf][3] = __float_as_uint(ap[8 * ASK + 4]); // (g+8,    t4+4)
            }
#pragma unroll
            for (int nf = 0; nf < 4; nf++) {
                const float* bp = &bs[(kb + t4) * BNS + wn * 32 + nf * 8 + g];
                bf[nf][0] = __float_as_uint(bp[0]);           // (t4,   g)
                bf[nf][1] = __float_as_uint(bp[4 * BNS]);     // (t4+4, g)
            }
#pragma unroll
            for (int mf = 0; mf < 4; mf++)
#pragma unroll
                for (int nf = 0; nf < 4; nf++)
                    mma_tf32(c[mf][nf], af[mf], bf[nf]);
        }

        // publish prefetched tile into the other buffer
        if (t + 1 < NKT) {
#pragma unroll
            for (int l = 0; l < 2; l++) {
                *(float4*)&As[buf ^ 1][am[l] * ASK + akq[l]] =
                    make_float4(tf32r(pa[l].x), tf32r(pa[l].y), tf32r(pa[l].z), tf32r(pa[l].w));
                *(float4*)&Bs[buf ^ 1][wk[l] * BNS + wn4[l]] =
                    make_float4(tf32r(pb[l].x), tf32r(pb[l].y), tf32r(pb[l].z), tf32r(pb[l].w));
            }
            __syncthreads();
        }
    }

    // ---- epilogue ----
    // frag (mf,nf): rows row0+wm*64+mf*16+{g, g+8}, cols col0+wn*32+nf*8+2*t4+{0,1}
#pragma unroll
    for (int mf = 0; mf < 4; mf++) {
#pragma unroll
        for (int nf = 0; nf < 4; nf++) {
            int col = col0 + wn * 32 + nf * 8 + 2 * t4;
            float b0 = bias[col], b1 = bias[col + 1];
#pragma unroll
            for (int half = 0; half < 2; half++) {
                int row = row0 + wm * 64 + mf * 16 + g + half * 8;
                float v0 = c[mf][nf][2 * half + 0] + b0;
                float v1 = c[mf][nf][2 * half + 1] + b1;
                if (!scatter) {
                    *(float2*)&out[(size_t)row * N + col] = make_float2(v0, v1);
                } else {
                    int which = col >> 10;
                    int cc    = col & 1023;
                    int h     = cc >> 6;
                    int dbase = cc & 63;        // even, so col+1 stays in-head
                    float* dst = (which == 0) ? g_q : ((which == 1) ? g_k : g_v);
                    int b = row >> 11;
                    int tt = row & 2047;
                    size_t base = (((size_t)(b * NHEADS + h) * TSEQ) + tt) * HD + dbase;
                    *(float2*)&dst[base] = make_float2(v0, v1);
                }
            }
        }
    }
}

// ---------------- Flash attention (causal), fp32 ----------------------------
// grid = (T/64, B*H), 256 threads. Thread (r=tid/16, c=tid%16) owns
// S rows {r,r+16,r+32,r+48} x cols {c,c+16,c+32,c+48}, O cols d=4c..4c+3.
// P tile lives in SMEM pre-duplicated as {p,p} u64 pairs (PV loop has zero
// packing MOVs). K/V tiles are cp.async ping-ponged in place: K(kt+1) loads
// during the PV loop (Ks dead after mid-barrier), V(kt+1) loads during the
// next QK loop (Vs dead after end barrier). qt is reversed so the heaviest
// causal tiles are scheduled first (LPT).
#define AST 68     // Q/K/V smem row stride (floats): 16B-aligned, low-conflict
#define PST 66     // P smem row stride (u64)
#define ATTN_SMEM (3 * 64 * AST * 4 + 64 * PST * 8)   // 85760 B

__global__ __launch_bounds__(256, 2)
void csa_attn_kernel()
{
    extern __shared__ float sm[];
    float* Qs = sm;
    float* Ks = sm + 64 * AST;
    float* Vs = sm + 2 * 64 * AST;
    u64*   Ps = (u64*)(sm + 3 * 64 * AST);

    int bh  = blockIdx.y;
    int qt  = gridDim.x - 1 - blockIdx.x;   // heaviest-first scheduling
    int tid = threadIdx.x;
    int r = tid >> 4, c = tid & 15;

    const float* qb = g_q + (size_t)bh * TSEQ * HD;
    const float* kb = g_k + (size_t)bh * TSEQ * HD;
    const float* vb = g_v + (size_t)bh * TSEQ * HD;
    int q0 = qt * 64;

    // per-thread loader slice: 4 rows x one float4 each (row = tid/16 + 16l)
    int lrowi[4], lc4;
    lc4 = (tid & 15) << 2;
#pragma unroll
    for (int l = 0; l < 4; l++) lrowi[l] = (tid >> 4) + 16 * l;

    // load Q tile (64x64) + async K0,V0
#pragma unroll
    for (int l = 0; l < 4; l++) {
        int row = lrowi[l];
        *(float4*)&Qs[row * AST + lc4] =
            *(const float4*)&qb[(size_t)(q0 + row) * HD + lc4];
        cpa16(&Ks[row * AST + lc4], &kb[(size_t)row * HD + lc4]);
        cpa16(&Vs[row * AST + lc4], &vb[(size_t)row * HD + lc4]);
    }
    cpa_commit();

    float mrow[4], lrow[4];
    u64 oac[4][2];
#pragma unroll
    for (int i = 0; i < 4; i++) {
        mrow[i] = -1e30f; lrow[i] = 0.0f;
        oac[i][0] = 0ull; oac[i][1] = 0ull;
    }

    const float SC = 0.125f * 1.4426950408889634f;  // 1/sqrt(64) * log2(e)

    for (int kt = 0; kt <= qt; ++kt) {
        // pending cp.async for this iteration's K (and V) must land
        cpa_wait0();
        __syncthreads();

        // S = Q K^T : f32x2 pair-accumulate along d, operands pre-packed in smem
        u64 sac[4][4];
#pragma unroll
        for (int i = 0; i < 4; i++)
#pragma unroll
            for (int j = 0; j < 4; j++) sac[i][j] = 0ull;

#pragma unroll
        for (int d4 = 0; d4 < 16; ++d4) {
            ulonglong2 qv[4], kv[4];
#pragma unroll
            for (int i = 0; i < 4; i++)
                qv[i] = *(const ulonglong2*)&Qs[(r + 16 * i) * AST + d4 * 4];
#pragma unroll
            for (int j = 0; j < 4; j++)
                kv[j] = *(const ulonglong2*)&Ks[(c + 16 * j) * AST + d4 * 4];
#pragma unroll
            for (int i = 0; i < 4; i++)
#pragma unroll
                for (int j = 0; j < 4; j++) {
                    ffma2(sac[i][j], qv[i].x, kv[j].x);
                    ffma2(sac[i][j], qv[i].y, kv[j].y);
                }
        }

        // online softmax (log2 domain, bare MUFU.EX2)
        int k0 = kt * 64;
        float p[4][4], alpha[4];
#pragma unroll
        for (int i = 0; i < 4; i++) {
            int qrow = q0 + r + 16 * i;
            float sv[4];
#pragma unroll
            for (int j = 0; j < 4; j++) {
                float a, b; upk(sac[i][j], a, b);
                float s = (a + b) * SC;
                int kcol = k0 + c + 16 * j;
                sv[j] = (kcol <= qrow) ? s : -1e30f;
            }
            float mloc = fmaxf(fmaxf(sv[0], sv[1]), fmaxf(sv[2], sv[3]));
#pragma unroll
            for (int w = 1; w < 16; w <<= 1)
                mloc = fmaxf(mloc, __shfl_xor_sync(0xffffffffu, mloc, w, 16));
            float mnew = fmaxf(mrow[i], mloc);
            float al = ex2(mrow[i] - mnew);
            mrow[i] = mnew;
            float ps = 0.0f;
#pragma unroll
            for (int j = 0; j < 4; j++) { p[i][j] = ex2(sv[j] - mnew); ps += p[i][j]; }
#pragma unroll
            for (int w = 1; w < 16; w <<= 1)
                ps += __shfl_xor_sync(0xffffffffu, ps, w, 16);
            lrow[i] = lrow[i] * al + ps;
            alpha[i] = al;
        }
        // rescale running O
#pragma unroll
        for (int i = 0; i < 4; i++) {
            u64 ap = pkdup(alpha[i]);
            fmul2(oac[i][0], ap);
            fmul2(oac[i][1], ap);
        }
        // publish P pre-duplicated as {p,p} pairs
#pragma unroll
        for (int i = 0; i < 4; i++)
#pragma unroll
            for (int j = 0; j < 4; j++)
                Ps[(r + 16 * i) * PST + (c + 16 * j)] = pkdup(p[i][j]);
        __syncthreads();   // publishes P; everyone is also done reading Ks

        // Ks is dead now: overlap K(kt+1) load with the PV loop below
        if (kt + 1 <= qt) {
            int kn0 = (kt + 1) * 64;
#pragma unroll
            for (int l = 0; l < 4; l++) {
                int row = lrowi[l];
                cpa16(&Ks[row * AST + lc4], &kb[(size_t)(kn0 + row) * HD + lc4]);
            }
            cpa_commit();
        }

        // O += P @ V  (thread owns d = 4c..4c+3); P loads are LDS.64 broadcast
#pragma unroll 4
        for (int jj = 0; jj < 64; ++jj) {
            ulonglong2 vv = *(const ulonglong2*)&Vs[jj * AST + (c << 2)];
#pragma unroll
            for (int i = 0; i < 4; i++) {
                u64 pd = Ps[(r + 16 * i) * PST + jj];
                ffma2(oac[i][0], pd, vv.x);
                ffma2(oac[i][1], pd, vv.y);
            }
        }
        __syncthreads();   // everyone done reading Vs and Ps

        // Vs is dead now: overlap V(kt+1) load with the next iteration's QK
        if (kt + 1 <= qt) {
            int kn0 = (kt + 1) * 64;
#pragma unroll
            for (int l = 0; l < 4; l++) {
                int row = lrowi[l];
                cpa16(&Vs[row * AST + lc4], &vb[(size_t)(kn0 + row) * HD + lc4]);
            }
            cpa_commit();
        }
    }

    // epilogue: normalize, write [B,T,C]
    int b = bh >> 4, h = bh & 15;
#pragma unroll
    for (int i = 0; i < 4; i++) {
        float inv = 1.0f / lrow[i];
        float o0, o1, o2, o3;
        upk(oac[i][0], o0, o1);
        upk(oac[i][1], o2, o3);
        int qrow = q0 + r + 16 * i;
        *(float4*)&g_att[((size_t)(b * TSEQ + qrow)) * HIDDEN + h * HD + (c << 2)] =
            make_float4(o0 * inv, o1 * inv, o2 * inv, o3 * inv);
    }
}

// ---------------- launch -----------------------------------------------------
extern "C" void kernel_launch(void* const* d_in, const int* in_sizes, int n_in,
                              void* d_out, int out_size)
{
    const float* x     = (const float*)d_in[0];
    const float* w_qkv = (const float*)d_in[1];
    const float* b_qkv = (const float*)d_in[2];
    const float* w_out = (const float*)d_in[3];
    const float* b_out = (const float*)d_in[4];
    float* out = (float*)d_out;

    cudaFuncSetAttribute(csa_attn_kernel,
                         cudaFuncAttributeMaxDynamicSharedMemorySize, ATTN_SMEM);

    dim3 blk(256);
    // 1) QKV GEMM (tf32 tensor) + bias, scattered into [B,H,T,D] q/k/v scratch
    csa_gemm_tf32<<<dim3((3 * HIDDEN) / GBN, MROWS / GBM), blk>>>(
        x, w_qkv, b_qkv, nullptr, 3 * HIDDEN, 1);
    // 2) causal flash attention -> g_att [B,T,C]
    csa_attn_kernel<<<dim3(TSEQ / 64, BB * NHEADS), blk, ATTN_SMEM>>>();
    // 3) output projection (tf32 tensor) + bias -> d_out
    csa_gemm_tf32<<<dim3(HIDDEN / GBN, MROWS / GBM), blk>>>(
        nullptr, w_out, b_out, out, HIDDEN, 0);
}

// round 8
// speedup vs baseline: 3.1501x; 1.7989x over previous
#include <cuda_runtime.h>
#include <cstdint>

// Problem constants
#define HIDDEN  1024
#define NHEADS  16
#define HD      64
#define BB      2
#define TSEQ    2048
#define MROWS   (BB * TSEQ)          // 4096

// ---------------- scratch (device globals: no allocation allowed) ----------
__device__ float g_q[BB * NHEADS * TSEQ * HD];     // [B,H,T,D]
__device__ float g_k[BB * NHEADS * TSEQ * HD];     // [B,H,D,T]  (TRANSPOSED)
__device__ float g_v[BB * NHEADS * TSEQ * HD];     // [B,H,T,D]
__device__ float g_att[MROWS * HIDDEN];            // [B,T,C]

typedef unsigned long long u64;

// ---------------- helpers ----------------------------------------------------
__device__ __forceinline__ float ex2(float x) {
    float r; asm("ex2.approx.f32 %0, %1;" : "=f"(r) : "f"(x)); return r;
}
__device__ __forceinline__ void cpa16(void* s, const void* g) {
    unsigned sa = (unsigned)__cvta_generic_to_shared(s);
    asm volatile("cp.async.cg.shared.global [%0], [%1], 16;\n" :: "r"(sa), "l"(g));
}
__device__ __forceinline__ void cpa_commit() {
    asm volatile("cp.async.commit_group;\n");
}
__device__ __forceinline__ void cpa_wait0() {
    asm volatile("cp.async.wait_group 0;\n");
}
__device__ __forceinline__ float tf32r(float x) {
    float r; asm("cvt.rna.tf32.f32 %0, %1;" : "=f"(r) : "f"(x)); return r;
}
// m16n8k8 tf32 MMA, fp32 accumulate (validated on HW in round 7)
__device__ __forceinline__ void mma_tf32(float* c, const uint32_t* a, const uint32_t* b) {
    asm volatile(
        "mma.sync.aligned.m16n8k8.row.col.f32.tf32.tf32.f32 "
        "{%0,%1,%2,%3}, {%4,%5,%6,%7}, {%8,%9}, {%0,%1,%2,%3};\n"
        : "+f"(c[0]), "+f"(c[1]), "+f"(c[2]), "+f"(c[3])
        : "r"(a[0]), "r"(a[1]), "r"(a[2]), "r"(a[3]), "r"(b[0]), "r"(b[1]));
}

// ---------------- GEMM (tf32 tensor): out[M,N] = A[M,1024]@W[1024,N]+bias ---
// Identical to the round-7 passing kernel EXCEPT: the K scatter (which==1)
// now writes K transposed as [B,H,D,T] for the attention B-fragments.
#define GBM 128
#define GBN 128
#define GBK 16
#define ASK 20     // As row stride (floats): banks (m*20+k)%32 all-distinct
#define BNS 136    // Bs row stride (floats): banks (k*136+n)%32 all-distinct
#define NKT (HIDDEN / GBK)  // 64 k-tiles

__global__ __launch_bounds__(256, 2)
void csa_gemm_tf32(const float* __restrict__ A, const float* __restrict__ W,
                   const float* __restrict__ bias, float* __restrict__ out,
                   int N, int scatter)
{
    __shared__ __align__(16) float As[2][GBM * ASK];   // [m][k]
    __shared__ __align__(16) float Bs[2][GBK * BNS];   // [k][n]

    const float* Ap = A ? A : (const float*)g_att;

    int tid  = threadIdx.x;
    int warp = tid >> 5, lane = tid & 31;
    int wm = warp >> 2, wn = warp & 3;      // 2 x 4 warp grid
    int g  = lane >> 2, t4 = lane & 3;      // groupid / quad-thread
    int row0 = blockIdx.y * GBM;
    int col0 = blockIdx.x * GBN;

    int am[2], akq[2], wk[2], wn4[2];
#pragma unroll
    for (int l = 0; l < 2; l++) {
        int idx = tid + l * 256;
        am[l]  = idx >> 2;
        akq[l] = (idx & 3) << 2;
        wk[l]  = idx >> 5;
        wn4[l] = (idx & 31) << 2;
    }

    float c[4][4][4];
#pragma unroll
    for (int mf = 0; mf < 4; mf++)
#pragma unroll
        for (int nf = 0; nf < 4; nf++)
#pragma unroll
            for (int e = 0; e < 4; e++) c[mf][nf][e] = 0.0f;

    float4 pa[2], pb[2];

#pragma unroll
    for (int l = 0; l < 2; l++) {
        pa[l] = *(const float4*)&Ap[(size_t)(row0 + am[l]) * HIDDEN + akq[l]];
        pb[l] = *(const float4*)&W[(size_t)wk[l] * N + col0 + wn4[l]];
    }
#pragma unroll
    for (int l = 0; l < 2; l++) {
        *(float4*)&As[0][am[l] * ASK + akq[l]] =
            make_float4(tf32r(pa[l].x), tf32r(pa[l].y), tf32r(pa[l].z), tf32r(pa[l].w));
        *(float4*)&Bs[0][wk[l] * BNS + wn4[l]] =
            make_float4(tf32r(pb[l].x), tf32r(pb[l].y), tf32r(pb[l].z), tf32r(pb[l].w));
    }
    __syncthreads();

    for (int t = 0; t < NKT; t++) {
        int buf = t & 1;
        if (t + 1 < NKT) {
            int k0 = (t + 1) * GBK;
#pragma unroll
            for (int l = 0; l < 2; l++) {
                pa[l] = *(const float4*)&Ap[(size_t)(row0 + am[l]) * HIDDEN + k0 + akq[l]];
                pb[l] = *(const float4*)&W[(size_t)(k0 + wk[l]) * N + col0 + wn4[l]];
            }
        }

        const float* as = As[buf];
        const float* bs = Bs[buf];
#pragma unroll
        for (int k8 = 0; k8 < 2; k8++) {
            int kb = k8 * 8;
            uint32_t af[4][4], bf[4][2];
#pragma unroll
            for (int mf = 0; mf < 4; mf++) {
                const float* ap = &as[(wm * 64 + mf * 16 + g) * ASK + kb + t4];
                af[mf][0] = __float_as_uint(ap[0]);
                af[mf][1] = __float_as_uint(ap[8 * ASK]);
                af[mf][2] = __float_as_uint(ap[4]);
                af[mf][3] = __float_as_uint(ap[8 * ASK + 4]);
            }
#pragma unroll
            for (int nf = 0; nf < 4; nf++) {
                const float* bp = &bs[(kb + t4) * BNS + wn * 32 + nf * 8 + g];
                bf[nf][0] = __float_as_uint(bp[0]);
                bf[nf][1] = __float_as_uint(bp[4 * BNS]);
            }
#pragma unroll
            for (int mf = 0; mf < 4; mf++)
#pragma unroll
                for (int nf = 0; nf < 4; nf++)
                    mma_tf32(c[mf][nf], af[mf], bf[nf]);
        }

        if (t + 1 < NKT) {
#pragma unroll
            for (int l = 0; l < 2; l++) {
                *(float4*)&As[buf ^ 1][am[l] * ASK + akq[l]] =
                    make_float4(tf32r(pa[l].x), tf32r(pa[l].y), tf32r(pa[l].z), tf32r(pa[l].w));
                *(float4*)&Bs[buf ^ 1][wk[l] * BNS + wn4[l]] =
                    make_float4(tf32r(pb[l].x), tf32r(pb[l].y), tf32r(pb[l].z), tf32r(pb[l].w));
            }
            __syncthreads();
        }
    }

    // ---- epilogue ----
#pragma unroll
    for (int mf = 0; mf < 4; mf++) {
#pragma unroll
        for (int nf = 0; nf < 4; nf++) {
            int col = col0 + wn * 32 + nf * 8 + 2 * t4;
            float b0 = bias[col], b1 = bias[col + 1];
#pragma unroll
            for (int half = 0; half < 2; half++) {
                int row = row0 + wm * 64 + mf * 16 + g + half * 8;
                float v0 = c[mf][nf][2 * half + 0] + b0;
                float v1 = c[mf][nf][2 * half + 1] + b1;
                if (!scatter) {
                    *(float2*)&out[(size_t)row * N + col] = make_float2(v0, v1);
                } else {
                    int which = col >> 10;
                    int cc    = col & 1023;
                    int h     = cc >> 6;
                    int dbase = cc & 63;        // even
                    int b = row >> 11;
                    int tt = row & 2047;
                    if (which == 1) {
                        // K transposed: [B,H,D,T]
                        size_t base = (((size_t)(b * NHEADS + h) * HD) + dbase) * TSEQ + tt;
                        g_k[base]        = v0;
                        g_k[base + TSEQ] = v1;
                    } else {
                        float* dst = (which == 0) ? g_q : g_v;
                        size_t base = (((size_t)(b * NHEADS + h) * TSEQ) + tt) * HD + dbase;
                        *(float2*)&dst[base] = make_float2(v0, v1);
                    }
                }
            }
        }
    }
}

// ---------------- Flash attention (causal), tf32 tensor ----------------------
// grid = (T/128, B*H), 256 threads = 8 warps, each owning a 16-row strip.
// QK and PV both run on m16n8k8 tf32 MMA. Q fragments live in registers for
// the whole kernel; P reuses the (dead) Q SMEM buffer. K is read from the
// TRANSPOSED [B,H,D,T] layout so its natural rows are B-fragments. Softmax is
// warp-local (width-4 shfl over the quad). cp.async ping-pong (K during PV,
// V during next QK) + heaviest-first (LPT) scheduling retained.
#define BQ  128
#define QST 68     // Q/P stride (floats): A-frag banks 4g+t4 all-distinct
#define KST 72     // K/V stride (floats): B-frag banks 8*t4+g all-distinct
#define ATTN_SMEM (BQ * QST * 4 + 2 * 64 * KST * 4)   // 34816 + 36864 = 71680 B

__global__ __launch_bounds__(256, 2)
void csa_attn_mma()
{
    extern __shared__ float sm[];
    float* QP = sm;                    // Q tile (init) then P tile (mainloop)
    float* Ks = sm + BQ * QST;         // [d][token] 64x64
    float* Vs = Ks + 64 * KST;         // [token][d] 64x64

    int bh  = blockIdx.y;
    int qt  = gridDim.x - 1 - blockIdx.x;   // heaviest-first
    int tid = threadIdx.x;
    int wid = tid >> 5, lane = tid & 31;
    int g = lane >> 2, t4 = lane & 3;
    int q0 = qt * BQ;
    int nkt = 2 * (qt + 1);                 // 64-col kv tiles needed

    const float* qb = g_q + (size_t)bh * TSEQ * HD;   // [t][d]
    const float* kb = g_k + (size_t)bh * HD * TSEQ;   // [d][t]  (transposed)
    const float* vb = g_v + (size_t)bh * TSEQ * HD;   // [t][d]

    // ---- load Q tile (128x64) into SMEM ----
#pragma unroll
    for (int l = 0; l < 8; l++) {
        int idx = tid + l * 256;
        int row = idx >> 4;
        int c4  = (idx & 15) << 2;
        *(float4*)&QP[row * QST + c4] =
            *(const float4*)&qb[(size_t)(q0 + row) * HD + c4];
    }
    __syncthreads();

    // ---- extract Q fragments (held in registers for all kt tiles) ----
    uint32_t qf[8][4];
    {
        const float* qpr = &QP[(wid * 16 + g) * QST];
#pragma unroll
        for (int k8 = 0; k8 < 8; k8++) {
            const float* ap = qpr + k8 * 8 + t4;
            qf[k8][0] = __float_as_uint(ap[0]);
            qf[k8][1] = __float_as_uint(ap[8 * QST]);
            qf[k8][2] = __float_as_uint(ap[4]);
            qf[k8][3] = __float_as_uint(ap[8 * QST + 4]);
        }
    }
    __syncthreads();   // QP now free for P

    // ---- async load K0 [d][t], V0 [t][d] ----
#pragma unroll
    for (int l = 0; l < 4; l++) {
        int idx = tid + l * 256;
        int row = idx >> 4;                // 0..63
        int c4  = (idx & 15) << 2;
        cpa16(&Ks[row * KST + c4], &kb[(size_t)row * TSEQ + 0 + c4]);
        cpa16(&Vs[row * KST + c4], &vb[(size_t)(0 + row) * HD + c4]);
    }
    cpa_commit();

    float m0 = -1e30f, m1 = -1e30f, l0 = 0.0f, l1 = 0.0f;
    float o[8][4];
#pragma unroll
    for (int nf = 0; nf < 8; nf++)
#pragma unroll
        for (int e = 0; e < 4; e++) o[nf][e] = 0.0f;

    const float SC = 0.125f * 1.4426950408889634f;   // 1/sqrt(64) * log2(e)
    int qrow0 = q0 + wid * 16 + g;
    int qrow1 = qrow0 + 8;

    for (int kt = 0; kt < nkt; ++kt) {
        cpa_wait0();
        __syncthreads();

        // ---- S = Q K^T via tensor MMA ----
        float s[8][4];
#pragma unroll
        for (int nf = 0; nf < 8; nf++)
#pragma unroll
            for (int e = 0; e < 4; e++) s[nf][e] = 0.0f;

#pragma unroll
        for (int k8 = 0; k8 < 8; k8++) {
            const float* krow = &Ks[(k8 * 8 + t4) * KST + g];
#pragma unroll
            for (int nf = 0; nf < 8; nf++) {
                uint32_t bf[2];
                bf[0] = __float_as_uint(krow[nf * 8]);
                bf[1] = __float_as_uint(krow[4 * KST + nf * 8]);
                mma_tf32(s[nf], qf[k8], bf);
            }
        }

        // ---- softmax (warp-local; rows qrow0/qrow1, cols spread over quad) --
        int k0 = kt * 64;
        bool diag = (kt >= nkt - 2);
        if (diag) {
#pragma unroll
            for (int nf = 0; nf < 8; nf++) {
                int colb = k0 + nf * 8 + 2 * t4;
                s[nf][0] = (colb     <= qrow0) ? s[nf][0] * SC : -1e30f;
                s[nf][1] = (colb + 1 <= qrow0) ? s[nf][1] * SC : -1e30f;
                s[nf][2] = (colb     <= qrow1) ? s[nf][2] * SC : -1e30f;
                s[nf][3] = (colb + 1 <= qrow1) ? s[nf][3] * SC : -1e30f;
            }
        } else {
#pragma unroll
            for (int nf = 0; nf < 8; nf++)
#pragma unroll
                for (int e = 0; e < 4; e++) s[nf][e] *= SC;
        }

        float mx0 = -1e30f, mx1 = -1e30f;
#pragma unroll
        for (int nf = 0; nf < 8; nf++) {
            mx0 = fmaxf(mx0, fmaxf(s[nf][0], s[nf][1]));
            mx1 = fmaxf(mx1, fmaxf(s[nf][2], s[nf][3]));
        }
        mx0 = fmaxf(mx0, __shfl_xor_sync(0xffffffffu, mx0, 1, 4));
        mx0 = fmaxf(mx0, __shfl_xor_sync(0xffffffffu, mx0, 2, 4));
        mx1 = fmaxf(mx1, __shfl_xor_sync(0xffffffffu, mx1, 1, 4));
        mx1 = fmaxf(mx1, __shfl_xor_sync(0xffffffffu, mx1, 2, 4));

        float mn0 = fmaxf(m0, mx0), mn1 = fmaxf(m1, mx1);
        float al0 = ex2(m0 - mn0),  al1 = ex2(m1 - mn1);
        m0 = mn0; m1 = mn1;

        float ps0 = 0.0f, ps1 = 0.0f;
#pragma unroll
        for (int nf = 0; nf < 8; nf++) {
            s[nf][0] = ex2(s[nf][0] - m0);
            s[nf][1] = ex2(s[nf][1] - m0);
            s[nf][2] = ex2(s[nf][2] - m1);
            s[nf][3] = ex2(s[nf][3] - m1);
            ps0 += s[nf][0] + s[nf][1];
            ps1 += s[nf][2] + s[nf][3];
        }
        ps0 += __shfl_xor_sync(0xffffffffu, ps0, 1, 4);
        ps0 += __shfl_xor_sync(0xffffffffu, ps0, 2, 4);
        ps1 += __shfl_xor_sync(0xffffffffu, ps1, 1, 4);
        ps1 += __shfl_xor_sync(0xffffffffu, ps1, 2, 4);
        l0 = l0 * al0 + ps0;
        l1 = l1 * al1 + ps1;

#pragma unroll
        for (int nf = 0; nf < 8; nf++) {
            o[nf][0] *= al0; o[nf][1] *= al0;
            o[nf][2] *= al1; o[nf][3] *= al1;
        }

        // ---- publish P (tf32-rounded) into QP ----
        {
            float* pr0 = &QP[(wid * 16 + g) * QST];
            float* pr1 = pr0 + 8 * QST;
#pragma unroll
            for (int nf = 0; nf < 8; nf++) {
                *(float2*)&pr0[nf * 8 + 2 * t4] =
                    make_float2(tf32r(s[nf][0]), tf32r(s[nf][1]));
                *(float2*)&pr1[nf * 8 + 2 * t4] =
                    make_float2(tf32r(s[nf][2]), tf32r(s[nf][3]));
            }
        }
        __syncthreads();   // P visible; all warps done reading Ks

        // Ks dead: prefetch K(kt+1) during PV
        if (kt + 1 < nkt) {
            int kn0 = (kt + 1) * 64;
#pragma unroll
            for (int l = 0; l < 4; l++) {
                int idx = tid + l * 256;
                int row = idx >> 4;
                int c4  = (idx & 15) << 2;
                cpa16(&Ks[row * KST + c4], &kb[(size_t)row * TSEQ + kn0 + c4]);
            }
            cpa_commit();
        }

        // ---- O += P V via tensor MMA ----
#pragma unroll
        for (int k8 = 0; k8 < 8; k8++) {
            uint32_t pf[4];
            const float* pp = &QP[(wid * 16 + g) * QST + k8 * 8 + t4];
            pf[0] = __float_as_uint(pp[0]);
            pf[1] = __float_as_uint(pp[8 * QST]);
            pf[2] = __float_as_uint(pp[4]);
            pf[3] = __float_as_uint(pp[8 * QST + 4]);
            const float* vrow = &Vs[(k8 * 8 + t4) * KST + g];
#pragma unroll
            for (int nf = 0; nf < 8; nf++) {
                uint32_t bf[2];
                bf[0] = __float_as_uint(vrow[nf * 8]);
                bf[1] = __float_as_uint(vrow[4 * KST + nf * 8]);
                mma_tf32(o[nf], pf, bf);
            }
        }
        __syncthreads();   // all warps done reading Vs and QP(P)

        // Vs dead: prefetch V(kt+1) during next QK
        if (kt + 1 < nkt) {
            int kn0 = (kt + 1) * 64;
#pragma unroll
            for (int l = 0; l < 4; l++) {
                int idx = tid + l * 256;
                int row = idx >> 4;
                int c4  = (idx & 15) << 2;
                cpa16(&Vs[row * KST + c4], &vb[(size_t)(kn0 + row) * HD + c4]);
            }
            cpa_commit();
        }
    }

    // ---- epilogue: normalize, write [B,T,C] ----
    float inv0 = 1.0f / l0, inv1 = 1.0f / l1;
    int b = bh >> 4, h = bh & 15;
#pragma unroll
    for (int nf = 0; nf < 8; nf++) {
        int col = h * HD + nf * 8 + 2 * t4;
        *(float2*)&g_att[(size_t)(b * TSEQ + qrow0) * HIDDEN + col] =
            make_float2(o[nf][0] * inv0, o[nf][1] * inv0);
        *(float2*)&g_att[(size_t)(b * TSEQ + qrow1) * HIDDEN + col] =
            make_float2(o[nf][2] * inv1, o[nf][3] * inv1);
    }
}

// ---------------- launch -----------------------------------------------------
extern "C" void kernel_launch(void* const* d_in, const int* in_sizes, int n_in,
                              void* d_out, int out_size)
{
    const float* x     = (const float*)d_in[0];
    const float* w_qkv = (const float*)d_in[1];
    const float* b_qkv = (const float*)d_in[2];
    const float* w_out = (const float*)d_in[3];
    const float* b_out = (const float*)d_in[4];
    float* out = (float*)d_out;

    cudaFuncSetAttribute(csa_attn_mma,
                         cudaFuncAttributeMaxDynamicSharedMemorySize, ATTN_SMEM);

    dim3 blk(256);
    // 1) QKV GEMM (tf32 tensor) + bias -> q [T,D], k [D,T] (transposed), v [T,D]
    csa_gemm_tf32<<<dim3((3 * HIDDEN) / GBN, MROWS / GBM), blk>>>(
        x, w_qkv, b_qkv, nullptr, 3 * HIDDEN, 1);
    // 2) causal flash attention (tf32 tensor) -> g_att [B,T,C]
    csa_attn_mma<<<dim3(TSEQ / BQ, BB * NHEADS), blk, ATTN_SMEM>>>();
    // 3) output projection (tf32 tensor) + bias -> d_out
    csa_gemm_tf32<<<dim3(HIDDEN / GBN, MROWS / GBM), blk>>>(
        nullptr, w_out, b_out, out, HIDDEN, 0);
}

// round 12
// speedup vs baseline: 3.2792x; 1.0410x over previous
#include <cuda_runtime.h>
#include <cstdint>

// Problem constants
#define HIDDEN  1024
#define NHEADS  16
#define HD      64
#define BB      2
#define TSEQ    2048
#define MROWS   (BB * TSEQ)          // 4096

// ---------------- scratch (device globals: no allocation allowed) ----------
__device__ float g_q[BB * NHEADS * TSEQ * HD];     // [B,H,T,D]
__device__ float g_k[BB * NHEADS * TSEQ * HD];     // [B,H,D,T]  (TRANSPOSED)
__device__ float g_v[BB * NHEADS * TSEQ * HD];     // [B,H,T,D]
__device__ float g_att[MROWS * HIDDEN];            // [B,T,C]

typedef unsigned long long u64;

// ---------------- helpers ----------------------------------------------------
__device__ __forceinline__ float ex2(float x) {
    float r; asm("ex2.approx.f32 %0, %1;" : "=f"(r) : "f"(x)); return r;
}
__device__ __forceinline__ void cpa16(void* s, const void* g) {
    unsigned sa = (unsigned)__cvta_generic_to_shared(s);
    asm volatile("cp.async.cg.shared.global [%0], [%1], 16;\n" :: "r"(sa), "l"(g));
}
__device__ __forceinline__ void cpa_commit() {
    asm volatile("cp.async.commit_group;\n");
}
__device__ __forceinline__ void cpa_wait0() {
    asm volatile("cp.async.wait_group 0;\n");
}
__device__ __forceinline__ void cpa_wait1() {
    asm volatile("cp.async.wait_group 1;\n");
}
__device__ __forceinline__ float tf32r(float x) {
    float r; asm("cvt.rna.tf32.f32 %0, %1;" : "=f"(r) : "f"(x)); return r;
}
__device__ __forceinline__ uint32_t f2u_tf32(float x) {
    return __float_as_uint(tf32r(x));
}
// m16n8k8 tf32 MMA, fp32 accumulate (HW-validated rounds 7-8)
__device__ __forceinline__ void mma_tf32(float* c, const uint32_t* a, const uint32_t* b) {
    asm volatile(
        "mma.sync.aligned.m16n8k8.row.col.f32.tf32.tf32.f32 "
        "{%0,%1,%2,%3}, {%4,%5,%6,%7}, {%8,%9}, {%0,%1,%2,%3};\n"
        : "+f"(c[0]), "+f"(c[1]), "+f"(c[2]), "+f"(c[3])
        : "r"(a[0]), "r"(a[1]), "r"(a[2]), "r"(a[3]), "r"(b[0]), "r"(b[1]));
}

// ---------------- GEMM (tf32 tensor): out[M,N] = A[M,1024]@W[1024,N]+bias ---
// BM=128, BN=128, BK=16, 256 threads = 8 warps (2m x 4n), warp tile 64x32.
// 3-stage cp.async ring (copies for tile t+2 issued before compute(t));
// tf32 rounding applied at fragment build (numerically identical to staging-
// side rounding). One __syncthreads per k-tile.
// scatter=1: N=3072 -> q [T,D], k [D,T] (transposed), v [T,D].
// scatter=0: N=1024, A==nullptr reads g_att; writes `out` row-major.
#define GBM 128
#define GBN 128
#define GBK 16
#define ASK 20     // As row stride (floats): A-frag banks all-distinct
#define BNS 136    // Bs row stride (floats): B-frag banks all-distinct
#define NKT (HIDDEN / GBK)  // 64 k-tiles
#define GSTG 3
#define A_STG (GBM * ASK)            // 2560 floats
#define B_STG (GBK * BNS)            // 2176 floats
#define GEMM_SMEM (GSTG * (A_STG + B_STG) * 4)   // 56832 B

__global__ __launch_bounds__(256, 2)
void csa_gemm_tf32(const float* __restrict__ A, const float* __restrict__ W,
                   const float* __restrict__ bias, float* __restrict__ out,
                   int N, int scatter)
{
    extern __shared__ __align__(16) float gsm[];
    float* Asb = gsm;                    // [GSTG][A_STG]
    float* Bsb = gsm + GSTG * A_STG;     // [GSTG][B_STG]

    const float* Ap = A ? A : (const float*)g_att;

    int tid  = threadIdx.x;
    int warp = tid >> 5, lane = tid & 31;
    int wm = warp >> 2, wn = warp & 3;      // 2 x 4 warp grid
    int g  = lane >> 2, t4 = lane & 3;      // groupid / quad-thread
    int row0 = blockIdx.y * GBM;
    int col0 = blockIdx.x * GBN;

    // copy indices (each thread: 2 cpa16 of A, 2 cpa16 of W per tile)
    int am[2], akq[2], wk[2], wn4[2];
#pragma unroll
    for (int l = 0; l < 2; l++) {
        int idx = tid + l * 256;          // 0..511
        am[l]  = idx >> 2;                // 0..127
        akq[l] = (idx & 3) << 2;          // 0,4,8,12
        wk[l]  = idx >> 5;                // 0..15
        wn4[l] = (idx & 31) << 2;         // 0..124
    }

    float c[4][4][4];
#pragma unroll
    for (int mf = 0; mf < 4; mf++)
#pragma unroll
        for (int nf = 0; nf < 4; nf++)
#pragma unroll
            for (int e = 0; e < 4; e++) c[mf][nf][e] = 0.0f;

    // ---- prologue: async-copy tiles 0 and 1 ----
#pragma unroll
    for (int s = 0; s < 2; s++) {
        int k0 = s * GBK;
        float* as = Asb + s * A_STG;
        float* bs = Bsb + s * B_STG;
#pragma unroll
        for (int l = 0; l < 2; l++) {
            cpa16(&as[am[l] * ASK + akq[l]],
                  &Ap[(size_t)(row0 + am[l]) * HIDDEN + k0 + akq[l]]);
            cpa16(&bs[wk[l] * BNS + wn4[l]],
                  &W[(size_t)(k0 + wk[l]) * N + col0 + wn4[l]]);
        }
        cpa_commit();
    }

    for (int t = 0; t < NKT; t++) {
        cpa_wait1();          // tile t landed (>=2 groups committed ahead)
        __syncthreads();      // all threads see it; stage (t+2)%3 is reusable

        // issue copy of tile t+2 (overlaps the compute below); always commit
        if (t + 2 < NKT) {
            int k0 = (t + 2) * GBK;
            int s  = (t + 2) % GSTG;
            float* as = Asb + s * A_STG;
            float* bs = Bsb + s * B_STG;
#pragma unroll
            for (int l = 0; l < 2; l++) {
                cpa16(&as[am[l] * ASK + akq[l]],
                      &Ap[(size_t)(row0 + am[l]) * HIDDEN + k0 + akq[l]]);
                cpa16(&bs[wk[l] * BNS + wn4[l]],
                      &W[(size_t)(k0 + wk[l]) * N + col0 + wn4[l]]);
            }
        }
        cpa_commit();         // possibly-empty group keeps wait accounting exact

        // ---- compute tile t (tf32 rounding at fragment build) ----
        const float* as = Asb + (t % GSTG) * A_STG;
        const float* bs = Bsb + (t % GSTG) * B_STG;
#pragma unroll
        for (int k8 = 0; k8 < 2; k8++) {
            int kb = k8 * 8;
            uint32_t af[4][4], bf[4][2];
#pragma unroll
            for (int mf = 0; mf < 4; mf++) {
                const float* ap = &as[(wm * 64 + mf * 16 + g) * ASK + kb + t4];
                af[mf][0] = f2u_tf32(ap[0]);
                af[mf][1] = f2u_tf32(ap[8 * ASK]);
                af[mf][2] = f2u_tf32(ap[4]);
                af[mf][3] = f2u_tf32(ap[8 * ASK + 4]);
            }
#pragma unroll
            for (int nf = 0; nf < 4; nf++) {
                const float* bp = &bs[(kb + t4) * BNS + wn * 32 + nf * 8 + g];
                bf[nf][0] = f2u_tf32(bp[0]);
                bf[nf][1] = f2u_tf32(bp[4 * BNS]);
            }
#pragma unroll
            for (int mf = 0; mf < 4; mf++)
#pragma unroll
                for (int nf = 0; nf < 4; nf++)
                    mma_tf32(c[mf][nf], af[mf], bf[nf]);
        }
    }

    // ---- epilogue ----
#pragma unroll
    for (int mf = 0; mf < 4; mf++) {
#pragma unroll
        for (int nf = 0; nf < 4; nf++) {
            int col = col0 + wn * 32 + nf * 8 + 2 * t4;
            float b0 = bias[col], b1 = bias[col + 1];
#pragma unroll
            for (int half = 0; half < 2; half++) {
                int row = row0 + wm * 64 + mf * 16 + g + half * 8;
                float v0 = c[mf][nf][2 * half + 0] + b0;
                float v1 = c[mf][nf][2 * half + 1] + b1;
                if (!scatter) {
                    *(float2*)&out[(size_t)row * N + col] = make_float2(v0, v1);
                } else {
                    int which = col >> 10;
                    int cc    = col & 1023;
                    int h     = cc >> 6;
                    int dbase = cc & 63;        // even
                    int b = row >> 11;
                    int tt = row & 2047;
                    if (which == 1) {
                        // K transposed: [B,H,D,T]
                        size_t base = (((size_t)(b * NHEADS + h) * HD) + dbase) * TSEQ + tt;
                        g_k[base]        = v0;
                        g_k[base + TSEQ] = v1;
                    } else {
                        float* dst = (which == 0) ? g_q : g_v;
                        size_t base = (((size_t)(b * NHEADS + h) * TSEQ) + tt) * HD + dbase;
                        *(float2*)&dst[base] = make_float2(v0, v1);
                    }
                }
            }
        }
    }
}

// ---------------- Flash attention (causal), tf32 tensor ----------------------
// grid = (T/128, B*H), 256 threads = 8 warps, 16-row strips. QK and PV on
// m16n8k8 tf32 MMA; Q fragments register-resident; P reuses the dead Q SMEM.
// SPLIT K/V cp.async groups: at loop top wait_group(1) drains only K(kt) so
// the V(kt) copy stays in flight through QK+softmax; wait_group(0) lands V
// just before the publish-P barrier (whose fence makes all threads' V copies
// CTA-visible for PV). K(kt+1) prefetch overlaps PV; V(kt+1) overlaps the
// next QK. Heaviest-first (LPT) scheduling retained.
#define BQ  128
#define QST 68     // Q/P stride (floats): A-frag banks 4g+t4 all-distinct
#define KST 72     // K/V stride (floats): B-frag banks 8*t4+g all-distinct
#define ATTN_SMEM (BQ * QST * 4 + 2 * 64 * KST * 4)   // 71680 B

__global__ __launch_bounds__(256, 2)
void csa_attn_mma()
{
    extern __shared__ float sm[];
    float* QP = sm;                    // Q tile (init) then P tile (mainloop)
    float* Ks = sm + BQ * QST;         // [d][token] 64x64
    float* Vs = Ks + 64 * KST;         // [token][d] 64x64

    int bh  = blockIdx.y;
    int qt  = gridDim.x - 1 - blockIdx.x;   // heaviest-first
    int tid = threadIdx.x;
    int wid = tid >> 5, lane = tid & 31;
    int g = lane >> 2, t4 = lane & 3;
    int q0 = qt * BQ;
    int nkt = 2 * (qt + 1);                 // 64-col kv tiles needed

    const float* qb = g_q + (size_t)bh * TSEQ * HD;   // [t][d]
    const float* kb = g_k + (size_t)bh * HD * TSEQ;   // [d][t]  (transposed)
    const float* vb = g_v + (size_t)bh * TSEQ * HD;   // [t][d]

    // ---- load Q tile (128x64) into SMEM ----
#pragma unroll
    for (int l = 0; l < 8; l++) {
        int idx = tid + l * 256;
        int row = idx >> 4;
        int c4  = (idx & 15) << 2;
        *(float4*)&QP[row * QST + c4] =
            *(const float4*)&qb[(size_t)(q0 + row) * HD + c4];
    }
    __syncthreads();

    // ---- extract Q fragments (held in registers for all kt tiles) ----
    uint32_t qf[8][4];
    {
        const float* qpr = &QP[(wid * 16 + g) * QST];
#pragma unroll
        for (int k8 = 0; k8 < 8; k8++) {
            const float* ap = qpr + k8 * 8 + t4;
            qf[k8][0] = __float_as_uint(ap[0]);
            qf[k8][1] = __float_as_uint(ap[8 * QST]);
            qf[k8][2] = __float_as_uint(ap[4]);
            qf[k8][3] = __float_as_uint(ap[8 * QST + 4]);
        }
    }
    __syncthreads();   // QP now free for P

    // ---- async load K0 then V0 as SEPARATE groups (K older, V newer) ----
#pragma unroll
    for (int l = 0; l < 4; l++) {
        int idx = tid + l * 256;
        int row = idx >> 4;                // 0..63
        int c4  = (idx & 15) << 2;
        cpa16(&Ks[row * KST + c4], &kb[(size_t)row * TSEQ + 0 + c4]);
    }
    cpa_commit();
#pragma unroll
    for (int l = 0; l < 4; l++) {
        int idx = tid + l * 256;
        int row = idx >> 4;
        int c4  = (idx & 15) << 2;
        cpa16(&Vs[row * KST + c4], &vb[(size_t)(0 + row) * HD + c4]);
    }
    cpa_commit();

    float m0 = -1e30f, m1 = -1e30f, l0 = 0.0f, l1 = 0.0f;
    float o[8][4];
#pragma unroll
    for (int nf = 0; nf < 8; nf++)
#pragma unroll
        for (int e = 0; e < 4; e++) o[nf][e] = 0.0f;

    const float SC = 0.125f * 1.4426950408889634f;   // 1/sqrt(64) * log2(e)
    int qrow0 = q0 + wid * 16 + g;
    int qrow1 = qrow0 + 8;

    for (int kt = 0; kt < nkt; ++kt) {
        // In flight here: K(kt) [older], V(kt) [newer]. Drain K only.
        cpa_wait1();
        __syncthreads();   // K(kt) visible CTA-wide; V(kt) still loading

        // ---- S = Q K^T via tensor MMA (V load overlaps this + softmax) ----
        float s[8][4];
#pragma unroll
        for (int nf = 0; nf < 8; nf++)
#pragma unroll
            for (int e = 0; e < 4; e++) s[nf][e] = 0.0f;

#pragma unroll
        for (int k8 = 0; k8 < 8; k8++) {
            const float* krow = &Ks[(k8 * 8 + t4) * KST + g];
#pragma unroll
            for (int nf = 0; nf < 8; nf++) {
                uint32_t bf[2];
                bf[0] = __float_as_uint(krow[nf * 8]);
                bf[1] = __float_as_uint(krow[4 * KST + nf * 8]);
                mma_tf32(s[nf], qf[k8], bf);
            }
        }

        // ---- softmax (warp-local; rows qrow0/qrow1, cols spread over quad) --
        int k0 = kt * 64;
        bool diag = (kt >= nkt - 2);
        if (diag) {
#pragma unroll
            for (int nf = 0; nf < 8; nf++) {
                int colb = k0 + nf * 8 + 2 * t4;
                s[nf][0] = (colb     <= qrow0) ? s[nf][0] * SC : -1e30f;
                s[nf][1] = (colb + 1 <= qrow0) ? s[nf][1] * SC : -1e30f;
                s[nf][2] = (colb     <= qrow1) ? s[nf][2] * SC : -1e30f;
                s[nf][3] = (colb + 1 <= qrow1) ? s[nf][3] * SC : -1e30f;
            }
        } else {
#pragma unroll
            for (int nf = 0; nf < 8; nf++)
#pragma unroll
                for (int e = 0; e < 4; e++) s[nf][e] *= SC;
        }

        float mx0 = -1e30f, mx1 = -1e30f;
#pragma unroll
        for (int nf = 0; nf < 8; nf++) {
            mx0 = fmaxf(mx0, fmaxf(s[nf][0], s[nf][1]));
            mx1 = fmaxf(mx1, fmaxf(s[nf][2], s[nf][3]));
        }
        mx0 = fmaxf(mx0, __shfl_xor_sync(0xffffffffu, mx0, 1, 4));
        mx0 = fmaxf(mx0, __shfl_xor_sync(0xffffffffu, mx0, 2, 4));
        mx1 = fmaxf(mx1, __shfl_xor_sync(0xffffffffu, mx1, 1, 4));
        mx1 = fmaxf(mx1, __shfl_xor_sync(0xffffffffu, mx1, 2, 4));

        float mn0 = fmaxf(m0, mx0), mn1 = fmaxf(m1, mx1);
        float al0 = ex2(m0 - mn0),  al1 = ex2(m1 - mn1);
        m0 = mn0; m1 = mn1;

        float ps0 = 0.0f, ps1 = 0.0f;
#pragma unroll
        for (int nf = 0; nf < 8; nf++) {
            s[nf][0] = ex2(s[nf][0] - m0);
            s[nf][1] = ex2(s[nf][1] - m0);
            s[nf][2] = ex2(s[nf][2] - m1);
            s[nf][3] = ex2(s[nf][3] - m1);
            ps0 += s[nf][0] + s[nf][1];
            ps1 += s[nf][2] + s[nf][3];
        }
        ps0 += __shfl_xor_sync(0xffffffffu, ps0, 1, 4);
        ps0 += __shfl_xor_sync(0xffffffffu, ps0, 2, 4);
        ps1 += __shfl_xor_sync(0xffffffffu, ps1, 1, 4);
        ps1 += __shfl_xor_sync(0xffffffffu, ps1, 2, 4);
        l0 = l0 * al0 + ps0;
        l1 = l1 * al1 + ps1;

#pragma unroll
        for (int nf = 0; nf < 8; nf++) {
            o[nf][0] *= al0; o[nf][1] *= al0;
            o[nf][2] *= al1; o[nf][3] *= al1;
        }

        // V(kt) must land before the barrier below (own copies done here;
        // the barrier's fence publishes everyone's to the CTA).
        cpa_wait0();

        // ---- publish P (tf32-rounded) into QP ----
        {
            float* pr0 = &QP[(wid * 16 + g) * QST];
            float* pr1 = pr0 + 8 * QST;
#pragma unroll
            for (int nf = 0; nf < 8; nf++) {
                *(float2*)&pr0[nf * 8 + 2 * t4] =
                    make_float2(tf32r(s[nf][0]), tf32r(s[nf][1]));
                *(float2*)&pr1[nf * 8 + 2 * t4] =
                    make_float2(tf32r(s[nf][2]), tf32r(s[nf][3]));
            }
        }
        __syncthreads();   // P + all V copies visible; Ks dead

        // Ks dead: prefetch K(kt+1) during PV (group committed BEFORE V's)
        if (kt + 1 < nkt) {
            int kn0 = (kt + 1) * 64;
#pragma unroll
            for (int l = 0; l < 4; l++) {
                int idx = tid + l * 256;
                int row = idx >> 4;
                int c4  = (idx & 15) << 2;
                cpa16(&Ks[row * KST + c4], &kb[(size_t)row * TSEQ + kn0 + c4]);
            }
            cpa_commit();
        }

        // ---- O += P V via tensor MMA ----
#pragma unroll
        for (int k8 = 0; k8 < 8; k8++) {
            uint32_t pf[4];
            const float* pp = &QP[(wid * 16 + g) * QST + k8 * 8 + t4];
            pf[0] = __float_as_uint(pp[0]);
            pf[1] = __float_as_uint(pp[8 * QST]);
            pf[2] = __float_as_uint(pp[4]);
            pf[3] = __float_as_uint(pp[8 * QST + 4]);
            const float* vrow = &Vs[(k8 * 8 + t4) * KST + g];
#pragma unroll
            for (int nf = 0; nf < 8; nf++) {
                uint32_t bf[2];
                bf[0] = __float_as_uint(vrow[nf * 8]);
                bf[1] = __float_as_uint(vrow[4 * KST + nf * 8]);
                mma_tf32(o[nf], pf, bf);
            }
        }
        __syncthreads();   // all warps done reading Vs and QP(P)

        // Vs dead: prefetch V(kt+1) during next QK (newer group than K's)
        if (kt + 1 < nkt) {
            int kn0 = (kt + 1) * 64;
#pragma unroll
            for (int l = 0; l < 4; l++) {
                int idx = tid + l * 256;
                int row = idx >> 4;
                int c4  = (idx & 15) << 2;
                cpa16(&Vs[row * KST + c4], &vb[(size_t)(kn0 + row) * HD + c4]);
            }
            cpa_commit();
        }
    }

    // ---- epilogue: normalize, write [B,T,C] ----
    float inv0 = 1.0f / l0, inv1 = 1.0f / l1;
    int b = bh >> 4, h = bh & 15;
#pragma unroll
    for (int nf = 0; nf < 8; nf++) {
        int col = h * HD + nf * 8 + 2 * t4;
        *(float2*)&g_att[(size_t)(b * TSEQ + qrow0) * HIDDEN + col] =
            make_float2(o[nf][0] * inv0, o[nf][1] * inv0);
        *(float2*)&g_att[(size_t)(b * TSEQ + qrow1) * HIDDEN + col] =
            make_float2(o[nf][2] * inv1, o[nf][3] * inv1);
    }
}

// ---------------- launch -----------------------------------------------------
extern "C" void kernel_launch(void* const* d_in, const int* in_sizes, int n_in,
                              void* d_out, int out_size)
{
    const float* x     = (const float*)d_in[0];
    const float* w_qkv = (const float*)d_in[1];
    const float* b_qkv = (const float*)d_in[2];
    const float* w_out = (const float*)d_in[3];
    const float* b_out = (const float*)d_in[4];
    float* out = (float*)d_out;

    cudaFuncSetAttribute(csa_attn_mma,
                         cudaFuncAttributeMaxDynamicSharedMemorySize, ATTN_SMEM);
    cudaFuncSetAttribute(csa_gemm_tf32,
                         cudaFuncAttributeMaxDynamicSharedMemorySize, GEMM_SMEM);

    dim3 blk(256);
    // 1) QKV GEMM (tf32 tensor) + bias -> q [T,D], k [D,T] (transposed), v [T,D]
    csa_gemm_tf32<<<dim3((3 * HIDDEN) / GBN, MROWS / GBM), blk, GEMM_SMEM>>>(
        x, w_qkv, b_qkv, nullptr, 3 * HIDDEN, 1);
    // 2) causal flash attention (tf32 tensor) -> g_att [B,T,C]
    csa_attn_mma<<<dim3(TSEQ / BQ, BB * NHEADS), blk, ATTN_SMEM>>>();
    // 3) output projection (tf32 tensor) + bias -> d_out
    csa_gemm_tf32<<<dim3(HIDDEN / GBN, MROWS / GBM), blk, GEMM_SMEM>>>(
        nullptr, w_out, b_out, out, HIDDEN, 0);
}

// round 17
// speedup vs baseline: 3.4580x; 1.0545x over previous
#include <cuda_runtime.h>
#include <cstdint>

// Problem constants
#define HIDDEN  1024
#define NHEADS  16
#define HD      64
#define BB      2
#define TSEQ    2048
#define MROWS   (BB * TSEQ)          // 4096

// ---------------- scratch (device globals: no allocation allowed) ----------
__device__ float g_q[BB * NHEADS * TSEQ * HD];     // [B,H,T,D]
__device__ float g_k[BB * NHEADS * TSEQ * HD];     // [B,H,T,D_perm]
__device__ float g_v[BB * NHEADS * TSEQ * HD];     // [B,H,D,T_perm]
__device__ float g_att[MROWS * HIDDEN];            // [B,T,C] (tf32-rounded)
__device__ float g_xr[MROWS * HIDDEN];             // tf32-rounded x
__device__ float g_wqkvr[HIDDEN * 3 * HIDDEN];     // tf32-rounded w_qkv
__device__ float g_woutr[HIDDEN * HIDDEN];         // tf32-rounded w_out

// ---------------- helpers ----------------------------------------------------
__device__ __forceinline__ float ex2(float x) {
    float r; asm("ex2.approx.f32 %0, %1;" : "=f"(r) : "f"(x)); return r;
}
__device__ __forceinline__ void cpa16(void* s, const void* g) {
    unsigned sa = (unsigned)__cvta_generic_to_shared(s);
    asm volatile("cp.async.cg.shared.global [%0], [%1], 16;\n" :: "r"(sa), "l"(g));
}
__device__ __forceinline__ void cpa_commit() {
    asm volatile("cp.async.commit_group;\n");
}
__device__ __forceinline__ void cpa_wait0() {
    asm volatile("cp.async.wait_group 0;\n");
}
__device__ __forceinline__ void cpa_wait1() {
    asm volatile("cp.async.wait_group 1;\n");
}
__device__ __forceinline__ float tf32r(float x) {
    float r; asm("cvt.rna.tf32.f32 %0, %1;" : "=f"(r) : "f"(x)); return r;
}
// fragment-pair permutation: within each 8-elem block, (c, c+4) land adjacent
__device__ __forceinline__ int perm8(int c) { return ((c & 3) << 1) | (c >> 2); }
// m16n8k8 tf32 MMA, fp32 accumulate (HW-validated rounds 7-12)
__device__ __forceinline__ void mma_tf32(float* c, const uint32_t* a, const uint32_t* b) {
    asm volatile(
        "mma.sync.aligned.m16n8k8.row.col.f32.tf32.tf32.f32 "
        "{%0,%1,%2,%3}, {%4,%5,%6,%7}, {%8,%9}, {%0,%1,%2,%3};\n"
        : "+f"(c[0]), "+f"(c[1]), "+f"(c[2]), "+f"(c[3])
        : "r"(a[0]), "r"(a[1]), "r"(a[2]), "r"(a[3]), "r"(b[0]), "r"(b[1]));
}

// ---------------- pre-round inputs to tf32 (numerics-identical move of CVT) -
__global__ void csa_round_tf32(const float4* __restrict__ in,
                               float4* __restrict__ out, int n4)
{
    int i = blockIdx.x * blockDim.x + threadIdx.x;
    int stride = gridDim.x * blockDim.x;
    for (; i < n4; i += stride) {
        float4 v = in[i];
        out[i] = make_float4(tf32r(v.x), tf32r(v.y), tf32r(v.z), tf32r(v.w));
    }
}

// ---------------- GEMM (tf32 tensor): out[M,N] = A[M,1024]@W[1024,N]+bias ---
// Inputs are PRE-ROUNDED to tf32 in gmem -> fragment build is raw bit loads
// (zero CVT in the mainloop). 3-stage cp.async ring, one barrier per k-tile.
// scatter=1: N=3072 -> q [T,D], k [T,D_perm], v [D,T_perm].
// scatter=0: N=1024, A==nullptr reads g_att (pre-rounded by attention).
#define GBM 128
#define GBN 128
#define GBK 16
#define ASK 20     // As row stride (floats)
#define BNS 136    // Bs row stride (floats)
#define NKT (HIDDEN / GBK)  // 64 k-tiles
#define GSTG 3
#define A_STG (GBM * ASK)            // 2560 floats
#define B_STG (GBK * BNS)            // 2176 floats
#define GEMM_SMEM (GSTG * (A_STG + B_STG) * 4)   // 56832 B

__global__ __launch_bounds__(256, 2)
void csa_gemm_tf32(const float* __restrict__ A, const float* __restrict__ W,
                   const float* __restrict__ bias, float* __restrict__ out,
                   int N, int scatter)
{
    extern __shared__ __align__(16) float gsm[];
    float* Asb = gsm;                    // [GSTG][A_STG]
    float* Bsb = gsm + GSTG * A_STG;     // [GSTG][B_STG]

    const float* Ap = A ? A : (const float*)g_att;

    int tid  = threadIdx.x;
    int warp = tid >> 5, lane = tid & 31;
    int wm = warp >> 2, wn = warp & 3;      // 2 x 4 warp grid
    int g  = lane >> 2, t4 = lane & 3;      // groupid / quad-thread
    int row0 = blockIdx.y * GBM;
    int col0 = blockIdx.x * GBN;

    int am[2], akq[2], wk[2], wn4[2];
#pragma unroll
    for (int l = 0; l < 2; l++) {
        int idx = tid + l * 256;
        am[l]  = idx >> 2;
        akq[l] = (idx & 3) << 2;
        wk[l]  = idx >> 5;
        wn4[l] = (idx & 31) << 2;
    }

    float c[4][4][4];
#pragma unroll
    for (int mf = 0; mf < 4; mf++)
#pragma unroll
        for (int nf = 0; nf < 4; nf++)
#pragma unroll
            for (int e = 0; e < 4; e++) c[mf][nf][e] = 0.0f;

    // ---- prologue: async-copy tiles 0 and 1 ----
#pragma unroll
    for (int s = 0; s < 2; s++) {
        int k0 = s * GBK;
        float* as = Asb + s * A_STG;
        float* bs = Bsb + s * B_STG;
#pragma unroll
        for (int l = 0; l < 2; l++) {
            cpa16(&as[am[l] * ASK + akq[l]],
                  &Ap[(size_t)(row0 + am[l]) * HIDDEN + k0 + akq[l]]);
            cpa16(&bs[wk[l] * BNS + wn4[l]],
                  &W[(size_t)(k0 + wk[l]) * N + col0 + wn4[l]]);
        }
        cpa_commit();
    }

    for (int t = 0; t < NKT; t++) {
        cpa_wait1();
        __syncthreads();

        if (t + 2 < NKT) {
            int k0 = (t + 2) * GBK;
            int s  = (t + 2) % GSTG;
            float* as = Asb + s * A_STG;
            float* bs = Bsb + s * B_STG;
#pragma unroll
            for (int l = 0; l < 2; l++) {
                cpa16(&as[am[l] * ASK + akq[l]],
                      &Ap[(size_t)(row0 + am[l]) * HIDDEN + k0 + akq[l]]);
                cpa16(&bs[wk[l] * BNS + wn4[l]],
                      &W[(size_t)(k0 + wk[l]) * N + col0 + wn4[l]]);
            }
        }
        cpa_commit();

        // ---- compute tile t (raw loads — inputs pre-rounded) ----
        const float* as = Asb + (t % GSTG) * A_STG;
        const float* bs = Bsb + (t % GSTG) * B_STG;
#pragma unroll
        for (int k8 = 0; k8 < 2; k8++) {
            int kb = k8 * 8;
            uint32_t af[4][4], bf[4][2];
#pragma unroll
            for (int mf = 0; mf < 4; mf++) {
                const float* ap = &as[(wm * 64 + mf * 16 + g) * ASK + kb + t4];
                af[mf][0] = __float_as_uint(ap[0]);
                af[mf][1] = __float_as_uint(ap[8 * ASK]);
                af[mf][2] = __float_as_uint(ap[4]);
                af[mf][3] = __float_as_uint(ap[8 * ASK + 4]);
            }
#pragma unroll
            for (int nf = 0; nf < 4; nf++) {
                const float* bp = &bs[(kb + t4) * BNS + wn * 32 + nf * 8 + g];
                bf[nf][0] = __float_as_uint(bp[0]);
                bf[nf][1] = __float_as_uint(bp[4 * BNS]);
            }
#pragma unroll
            for (int mf = 0; mf < 4; mf++)
#pragma unroll
                for (int nf = 0; nf < 4; nf++)
                    mma_tf32(c[mf][nf], af[mf], bf[nf]);
        }
    }

    // ---- epilogue ----
#pragma unroll
    for (int mf = 0; mf < 4; mf++) {
#pragma unroll
        for (int nf = 0; nf < 4; nf++) {
            int col = col0 + wn * 32 + nf * 8 + 2 * t4;
            float b0 = bias[col], b1 = bias[col + 1];
#pragma unroll
            for (int half = 0; half < 2; half++) {
                int row = row0 + wm * 64 + mf * 16 + g + half * 8;
                float v0 = c[mf][nf][2 * half + 0] + b0;
                float v1 = c[mf][nf][2 * half + 1] + b1;
                if (!scatter) {
                    *(float2*)&out[(size_t)row * N + col] = make_float2(v0, v1);
                } else {
                    int which = col >> 10;
                    int cc    = col & 1023;
                    int h     = cc >> 6;
                    int dbase = cc & 63;        // even
                    int b = row >> 11;
                    int tt = row & 2047;
                    if (which == 0) {
                        size_t base = (((size_t)(b * NHEADS + h) * TSEQ) + tt) * HD + dbase;
                        *(float2*)&g_q[base] = make_float2(v0, v1);
                    } else if (which == 1) {
                        // K: [B,H,T,D_perm] — d pairs (t4,t4+4) adjacent
                        size_t base = (((size_t)(b * NHEADS + h) * TSEQ) + tt) * HD;
                        g_k[base + (dbase & ~7) + perm8(dbase & 7)]           = v0;
                        g_k[base + ((dbase + 1) & ~7) + perm8((dbase + 1) & 7)] = v1;
                    } else {
                        // V: [B,H,D,T_perm] — token pairs adjacent
                        int tp = (tt & ~7) + perm8(tt & 7);
                        size_t base = (((size_t)(b * NHEADS + h) * HD) + dbase) * TSEQ + tp;
                        g_v[base]        = v0;
                        g_v[base + TSEQ] = v1;
                    }
                }
            }
        }
    }
}

// ---------------- Flash attention (causal), tf32 tensor ----------------------
// grid = (T/128, B*H), 256 threads = 8 warps, 16-row strips.
// Pair-permuted layouts: K smem [token][d_perm], V smem [d][token_perm],
// P smem [row][col_perm] — every B-/P-fragment pair is ONE LDS.64.
// Split K/V cp.async groups (V load overlaps QK+softmax). LPT scheduling.
// Epilogue rounds g_att to tf32 so the proj GEMM needs no CVT.
#define BQ  128
#define QST 72     // Q/P stride (floats)
#define KST 72     // K/V stride (floats)
#define ATTN_SMEM (BQ * QST * 4 + 2 * 64 * KST * 4)   // 36864 + 36864 = 73728 B

__global__ __launch_bounds__(256, 2)
void csa_attn_mma()
{
    extern __shared__ float sm[];
    float* QP = sm;                    // Q tile (init) then P tile (mainloop)
    float* Ks = sm + BQ * QST;         // [token][d_perm] 64x64
    float* Vs = Ks + 64 * KST;         // [d][token_perm] 64x64

    int bh  = blockIdx.y;
    int qt  = gridDim.x - 1 - blockIdx.x;   // heaviest-first
    int tid = threadIdx.x;
    int wid = tid >> 5, lane = tid & 31;
    int g = lane >> 2, t4 = lane & 3;
    int q0 = qt * BQ;
    int nkt = 2 * (qt + 1);                 // 64-col kv tiles needed

    const float* qb = g_q + (size_t)bh * TSEQ * HD;   // [t][d]
    const float* kb = g_k + (size_t)bh * TSEQ * HD;   // [t][d_perm]
    const float* vb = g_v + (size_t)bh * HD * TSEQ;   // [d][t_perm]

    // ---- load Q tile (128x64) into SMEM ----
#pragma unroll
    for (int l = 0; l < 8; l++) {
        int idx = tid + l * 256;
        int row = idx >> 4;
        int c4  = (idx & 15) << 2;
        *(float4*)&QP[row * QST + c4] =
            *(const float4*)&qb[(size_t)(q0 + row) * HD + c4];
    }
    __syncthreads();

    // ---- extract Q fragments (registers for all kt tiles; raw bits) ----
    uint32_t qf[8][4];
    {
        const float* qpr = &QP[(wid * 16 + g) * QST];
#pragma unroll
        for (int k8 = 0; k8 < 8; k8++) {
            const float* ap = qpr + k8 * 8 + t4;
            qf[k8][0] = __float_as_uint(ap[0]);
            qf[k8][1] = __float_as_uint(ap[8 * QST]);
            qf[k8][2] = __float_as_uint(ap[4]);
            qf[k8][3] = __float_as_uint(ap[8 * QST + 4]);
        }
    }
    __syncthreads();   // QP now free for P

    // ---- async load K0 then V0 as SEPARATE groups (K older, V newer) ----
#pragma unroll
    for (int l = 0; l < 4; l++) {
        int idx = tid + l * 256;
        int row = idx >> 4;                // 0..63
        int c4  = (idx & 15) << 2;
        cpa16(&Ks[row * KST + c4], &kb[(size_t)(0 + row) * HD + c4]);
    }
    cpa_commit();
#pragma unroll
    for (int l = 0; l < 4; l++) {
        int idx = tid + l * 256;
        int row = idx >> 4;
        int c4  = (idx & 15) << 2;
        cpa16(&Vs[row * KST + c4], &vb[(size_t)row * TSEQ + 0 + c4]);
    }
    cpa_commit();

    float m0 = -1e30f, m1 = -1e30f, l0 = 0.0f, l1 = 0.0f;
    float o[8][4];
#pragma unroll
    for (int nf = 0; nf < 8; nf++)
#pragma unroll
        for (int e = 0; e < 4; e++) o[nf][e] = 0.0f;

    const float SC = 0.125f * 1.4426950408889634f;   // 1/sqrt(64) * log2(e)
    int qrow0 = q0 + wid * 16 + g;
    int qrow1 = qrow0 + 8;
    int c2 = 2 * t4;                                  // permuted pair offset
    int pA = perm8(c2), pB = perm8(c2 + 1);           // P publish positions

    for (int kt = 0; kt < nkt; ++kt) {
        // In flight: K(kt) [older], V(kt) [newer]. Drain K only.
        cpa_wait1();
        __syncthreads();   // K(kt) visible; V(kt) still loading

        // ---- S = Q K^T : B-frag pairs are one LDS.64 from Ks[token][d_perm]
        float s[8][4];
#pragma unroll
        for (int nf = 0; nf < 8; nf++)
#pragma unroll
            for (int e = 0; e < 4; e++) s[nf][e] = 0.0f;

#pragma unroll
        for (int k8 = 0; k8 < 8; k8++) {
            int kbp = k8 * 8 + c2;
#pragma unroll
            for (int nf = 0; nf < 8; nf++) {
                float2 kv2 = *(const float2*)&Ks[(nf * 8 + g) * KST + kbp];
                uint32_t bf[2];
                bf[0] = __float_as_uint(kv2.x);   // K[tok][d=kb+t4]
                bf[1] = __float_as_uint(kv2.y);   // K[tok][d=kb+t4+4]
                mma_tf32(s[nf], qf[k8], bf);
            }
        }

        // ---- softmax (warp-local) ----
        int k0 = kt * 64;
        bool diag = (kt >= nkt - 2);
        if (diag) {
#pragma unroll
            for (int nf = 0; nf < 8; nf++) {
                int colb = k0 + nf * 8 + c2;
                s[nf][0] = (colb     <= qrow0) ? s[nf][0] * SC : -1e30f;
                s[nf][1] = (colb + 1 <= qrow0) ? s[nf][1] * SC : -1e30f;
                s[nf][2] = (colb     <= qrow1) ? s[nf][2] * SC : -1e30f;
                s[nf][3] = (colb + 1 <= qrow1) ? s[nf][3] * SC : -1e30f;
            }
        } else {
#pragma unroll
            for (int nf = 0; nf < 8; nf++)
#pragma unroll
                for (int e = 0; e < 4; e++) s[nf][e] *= SC;
        }

        float mx0 = -1e30f, mx1 = -1e30f;
#pragma unroll
        for (int nf = 0; nf < 8; nf++) {
            mx0 = fmaxf(mx0, fmaxf(s[nf][0], s[nf][1]));
            mx1 = fmaxf(mx1, fmaxf(s[nf][2], s[nf][3]));
        }
        mx0 = fmaxf(mx0, __shfl_xor_sync(0xffffffffu, mx0, 1, 4));
        mx0 = fmaxf(mx0, __shfl_xor_sync(0xffffffffu, mx0, 2, 4));
        mx1 = fmaxf(mx1, __shfl_xor_sync(0xffffffffu, mx1, 1, 4));
        mx1 = fmaxf(mx1, __shfl_xor_sync(0xffffffffu, mx1, 2, 4));

        float mn0 = fmaxf(m0, mx0), mn1 = fmaxf(m1, mx1);
        float al0 = ex2(m0 - mn0),  al1 = ex2(m1 - mn1);
        m0 = mn0; m1 = mn1;

        float ps0 = 0.0f, ps1 = 0.0f;
#pragma unroll
        for (int nf = 0; nf < 8; nf++) {
            s[nf][0] = ex2(s[nf][0] - m0);
            s[nf][1] = ex2(s[nf][1] - m0);
            s[nf][2] = ex2(s[nf][2] - m1);
            s[nf][3] = ex2(s[nf][3] - m1);
            ps0 += s[nf][0] + s[nf][1];
            ps1 += s[nf][2] + s[nf][3];
        }
        ps0 += __shfl_xor_sync(0xffffffffu, ps0, 1, 4);
        ps0 += __shfl_xor_sync(0xffffffffu, ps0, 2, 4);
        ps1 += __shfl_xor_sync(0xffffffffu, ps1, 1, 4);
        ps1 += __shfl_xor_sync(0xffffffffu, ps1, 2, 4);
        l0 = l0 * al0 + ps0;
        l1 = l1 * al1 + ps1;

#pragma unroll
        for (int nf = 0; nf < 8; nf++) {
            o[nf][0] *= al0; o[nf][1] *= al0;
            o[nf][2] *= al1; o[nf][3] *= al1;
        }

        // V(kt) must land before the publish barrier below.
        cpa_wait0();

        // ---- publish P (tf32-rounded) into QP, col-permuted ----
        {
            float* pr0 = &QP[(wid * 16 + g) * QST];
            float* pr1 = pr0 + 8 * QST;
#pragma unroll
            for (int nf = 0; nf < 8; nf++) {
                pr0[nf * 8 + pA] = tf32r(s[nf][0]);
                pr0[nf * 8 + pB] = tf32r(s[nf][1]);
                pr1[nf * 8 + pA] = tf32r(s[nf][2]);
                pr1[nf * 8 + pB] = tf32r(s[nf][3]);
            }
        }
        __syncthreads();   // P + all V copies visible; Ks dead

        // Ks dead: prefetch K(kt+1) during PV (group older than V's)
        if (kt + 1 < nkt) {
            int kn0 = (kt + 1) * 64;
#pragma unroll
            for (int l = 0; l < 4; l++) {
                int idx = tid + l * 256;
                int row = idx >> 4;
                int c4  = (idx & 15) << 2;
                cpa16(&Ks[row * KST + c4], &kb[(size_t)(kn0 + row) * HD + c4]);
            }
            cpa_commit();
        }

        // ---- O += P V : P pairs and V pairs are one LDS.64 each ----
#pragma unroll
        for (int k8 = 0; k8 < 8; k8++) {
            int kbp = k8 * 8 + c2;
            float2 pa0 = *(const float2*)&QP[(wid * 16 + g) * QST + kbp];
            float2 pa1 = *(const float2*)&QP[(wid * 16 + g + 8) * QST + kbp];
            uint32_t pf[4];
            pf[0] = __float_as_uint(pa0.x);   // P(g,   kb+t4)
            pf[1] = __float_as_uint(pa1.x);   // P(g+8, kb+t4)
            pf[2] = __float_as_uint(pa0.y);   // P(g,   kb+t4+4)
            pf[3] = __float_as_uint(pa1.y);   // P(g+8, kb+t4+4)
#pragma unroll
            for (int nf = 0; nf < 8; nf++) {
                float2 vv2 = *(const float2*)&Vs[(nf * 8 + g) * KST + kbp];
                uint32_t bf[2];
                bf[0] = __float_as_uint(vv2.x);   // V[tok=kb+t4][d]
                bf[1] = __float_as_uint(vv2.y);   // V[tok=kb+t4+4][d]
                mma_tf32(o[nf], pf, bf);
            }
        }
        __syncthreads();   // all warps done reading Vs and QP(P)

        // Vs dead: prefetch V(kt+1) during next QK (newer group)
        if (kt + 1 < nkt) {
            int kn0 = (kt + 1) * 64;
#pragma unroll
            for (int l = 0; l < 4; l++) {
                int idx = tid + l * 256;
                int row = idx >> 4;
                int c4  = (idx & 15) << 2;
                cpa16(&Vs[row * KST + c4], &vb[(size_t)row * TSEQ + kn0 + c4]);
            }
            cpa_commit();
        }
    }

    // ---- epilogue: normalize, tf32-round (for proj GEMM), write [B,T,C] ----
    float inv0 = 1.0f / l0, inv1 = 1.0f / l1;
    int b = bh >> 4, h = bh & 15;
#pragma unroll
    for (int nf = 0; nf < 8; nf++) {
        int col = h * HD + nf * 8 + c2;
        *(float2*)&g_att[(size_t)(b * TSEQ + qrow0) * HIDDEN + col] =
            make_float2(tf32r(o[nf][0] * inv0), tf32r(o[nf][1] * inv0));
        *(float2*)&g_att[(size_t)(b * TSEQ + qrow1) * HIDDEN + col] =
            make_float2(tf32r(o[nf][2] * inv1), tf32r(o[nf][3] * inv1));
    }
}

// ---------------- launch -----------------------------------------------------
extern "C" void kernel_launch(void* const* d_in, const int* in_sizes, int n_in,
                              void* d_out, int out_size)
{
    const float* x     = (const float*)d_in[0];
    const float* w_qkv = (const float*)d_in[1];
    const float* b_qkv = (const float*)d_in[2];
    const float* w_out = (const float*)d_in[3];
    const float* b_out = (const float*)d_in[4];
    float* out = (float*)d_out;

    cudaFuncSetAttribute(csa_attn_mma,
                         cudaFuncAttributeMaxDynamicSharedMemorySize, ATTN_SMEM);
    cudaFuncSetAttribute(csa_gemm_tf32,
                         cudaFuncAttributeMaxDynamicSharedMemorySize, GEMM_SMEM);

    // device-global scratch addresses (host-side symbol -> pointer)
    float *xr, *wqkvr, *woutr;
    cudaGetSymbolAddress((void**)&xr,    g_xr);
    cudaGetSymbolAddress((void**)&wqkvr, g_wqkvr);
    cudaGetSymbolAddress((void**)&woutr, g_woutr);

    dim3 blk(256);
    // 0) pre-round inputs to tf32 (moves ALL GEMM CVTs out of the mainloop)
    csa_round_tf32<<<1024, 256>>>((const float4*)x,     (float4*)xr,    MROWS * HIDDEN / 4);
    csa_round_tf32<<<1024, 256>>>((const float4*)w_qkv, (float4*)wqkvr, HIDDEN * 3 * HIDDEN / 4);
    csa_round_tf32<<<512, 256>>>((const float4*)w_out,  (float4*)woutr, HIDDEN * HIDDEN / 4);
    // 1) QKV GEMM -> q [T,D], k [T,D_perm], v [D,T_perm]
    csa_gemm_tf32<<<dim3((3 * HIDDEN) / GBN, MROWS / GBM), blk, GEMM_SMEM>>>(
        xr, wqkvr, b_qkv, nullptr, 3 * HIDDEN, 1);
    // 2) causal flash attention -> g_att [B,T,C] (tf32-rounded)
    csa_attn_mma<<<dim3(TSEQ / BQ, BB * NHEADS), blk, ATTN_SMEM>>>();
    // 3) output projection + bias -> d_out
    csa_gemm_tf32<<<dim3(HIDDEN / GBN, MROWS / GBM), blk, GEMM_SMEM>>>(
        nullptr, woutr, b_out, out, HIDDEN, 0);
}